// round 1
// baseline (speedup 1.0000x reference)
#include <cuda_runtime.h>
#include <cuda_bf16.h>
#include <math.h>
#include <float.h>

// ---------------------------------------------------------------------------
// Problem shape (fixed by setup_inputs): B=2, N=1000, K=8 neighbors
// ---------------------------------------------------------------------------
#define BATCH 2
#define NPTS  1000
#define KNN   8
#define NPAIR ((NPTS*(NPTS-1))/2)   // 499500

// ---------------------------------------------------------------------------
// Static scratch (no allocations allowed)
// ---------------------------------------------------------------------------
__device__ int   g_knn [BATCH*NPTS*KNN];
__device__ float g_E   [BATCH*NPTS*KNN*256];   // edge features, max 2C=256
__device__ float g_H   [BATCH*NPTS*KNN*256];   // hidden,      max 256
__device__ float g_Msg [BATCH*NPTS*KNN*512];   // messages,    max 512
__device__ float g_x1  [BATCH*NPTS*32];
__device__ float g_x2  [BATCH*NPTS*128];
__device__ float g_xcat[BATCH*NPTS*672];
__device__ float g_sf  [BATCH*NPTS*128];
__device__ float g_hi  [BATCH*NPTS*128];
__device__ float g_hj  [BATCH*NPTS*128];
__device__ float g_g   [BATCH*128];
__device__ float g_hg  [BATCH*128];

// ---------------------------------------------------------------------------
// kNN: per (b,n) block computes d2 to all m, keeps 8 smallest (ties -> lower idx)
// d2 = sq[n] + sq[m] - 2*dot  (matches reference formula)
// ---------------------------------------------------------------------------
template<int C>
__global__ void knn_kernel(const float* __restrict__ x, int* __restrict__ knn)
{
    const int b = blockIdx.y;
    const int n = blockIdx.x;
    const int tid = threadIdx.x;
    const int T = blockDim.x;   // 128
    const float* xb = x + (size_t)b * NPTS * C;

    __shared__ float xq[C];
    __shared__ float sd[128*8];
    __shared__ int   si[128*8];

    for (int c = tid; c < C; c += T) xq[c] = xb[(size_t)n*C + c];
    __syncthreads();

    float sqn = 0.f;
    #pragma unroll
    for (int c = 0; c < C; c++) sqn = fmaf(xq[c], xq[c], sqn);

    float bd[8]; int bi[8];
    #pragma unroll
    for (int k = 0; k < 8; k++) { bd[k] = FLT_MAX; bi[k] = 0x7FFFFFFF; }

    for (int m = tid; m < NPTS; m += T) {
        const float* xm = xb + (size_t)m * C;
        float dot = 0.f, sqm = 0.f;
        #pragma unroll
        for (int c = 0; c < C; c++) {
            float v = xm[c];
            dot = fmaf(xq[c], v, dot);
            sqm = fmaf(v, v, sqm);
        }
        float d = sqn + sqm - 2.f * dot;
        if (d < bd[7] || (d == bd[7] && m < bi[7])) {
            int p = 7;
            #pragma unroll
            for (int it = 0; it < 7; it++) {
                if (p > 0 && (d < bd[p-1] || (d == bd[p-1] && m < bi[p-1]))) {
                    bd[p] = bd[p-1]; bi[p] = bi[p-1]; p--;
                }
            }
            bd[p] = d; bi[p] = m;
        }
    }
    #pragma unroll
    for (int k = 0; k < 8; k++) { sd[tid*8+k] = bd[k]; si[tid*8+k] = bi[k]; }

    for (int s = T/2; s >= 1; s >>= 1) {
        __syncthreads();
        if (tid < s) {
            float* Ad = &sd[tid*8];        int* Ai = &si[tid*8];
            float* Bd = &sd[(tid+s)*8];    int* Bi = &si[(tid+s)*8];
            float od[8]; int oi[8];
            int a = 0, c2 = 0;
            #pragma unroll
            for (int o = 0; o < 8; o++) {
                bool ta = (Ad[a] < Bd[c2]) || (Ad[a] == Bd[c2] && Ai[a] < Bi[c2]);
                if (ta) { od[o] = Ad[a]; oi[o] = Ai[a]; a++; }
                else    { od[o] = Bd[c2]; oi[o] = Bi[c2]; c2++; }
            }
            #pragma unroll
            for (int o = 0; o < 8; o++) { Ad[o] = od[o]; Ai[o] = oi[o]; }
        }
    }
    __syncthreads();
    if (tid < 8) knn[((size_t)b*NPTS + n)*8 + tid] = si[tid];
}

// ---------------------------------------------------------------------------
// Build edge features: E[row] = [x_i , x_j - x_i], row = (b,n,k)
// ---------------------------------------------------------------------------
__global__ void build_edges_kernel(const float* __restrict__ x,
                                   const int* __restrict__ knn,
                                   int C, float* __restrict__ E)
{
    const int total = BATCH*NPTS*KNN*/*cols*/1;   // row count handled below
    (void)total;
    int t = blockIdx.x * blockDim.x + threadIdx.x;
    int all = BATCH*NPTS*KNN*C;
    if (t >= all) return;
    int c = t % C;
    int r = t / C;
    int n = (r / KNN) % NPTS;
    int b = r / (KNN*NPTS);
    int j = knn[r];
    float xi = x[(((size_t)b*NPTS) + n)*C + c];
    float xj = x[(((size_t)b*NPTS) + j)*C + c];
    E[(size_t)r*2*C + c]     = xi;
    E[(size_t)r*2*C + C + c] = xj - xi;
}

// ---------------------------------------------------------------------------
// Tiled SGEMM: C[M,N] = act(A[M,K] @ W[K,N] + bias)
// BM=BN=64, BK=8, 256 threads, 4x4 micro-tile
// ---------------------------------------------------------------------------
__global__ void sgemm_kernel(const float* __restrict__ A,
                             const float* __restrict__ W,
                             const float* __restrict__ bias,
                             float* __restrict__ C,
                             int M, int N, int K, int relu)
{
    const int BM = 64, BN = 64, BK = 8, TM = 4, TN = 4;
    __shared__ float As[BK][BM];
    __shared__ float Bs[BK][BN];

    int tid = threadIdx.x;
    int tx = tid % 16, ty = tid / 16;
    int row0 = blockIdx.y * BM;
    int col0 = blockIdx.x * BN;

    float acc[TM][TN];
    #pragma unroll
    for (int i = 0; i < TM; i++)
        #pragma unroll
        for (int j = 0; j < TN; j++) acc[i][j] = 0.f;

    for (int k0 = 0; k0 < K; k0 += BK) {
        #pragma unroll
        for (int i = tid; i < BM*BK; i += 256) {
            int m = i / BK, k = i % BK;
            int gm = row0 + m, gk = k0 + k;
            As[k][m] = (gm < M && gk < K) ? A[(size_t)gm*K + gk] : 0.f;
        }
        #pragma unroll
        for (int i = tid; i < BK*BN; i += 256) {
            int k = i / BN, n = i % BN;
            int gk = k0 + k, gn = col0 + n;
            Bs[k][n] = (gk < K && gn < N) ? W[(size_t)gk*N + gn] : 0.f;
        }
        __syncthreads();
        #pragma unroll
        for (int k = 0; k < BK; k++) {
            float ra[TM], rb[TN];
            #pragma unroll
            for (int i = 0; i < TM; i++) ra[i] = As[k][ty*TM + i];
            #pragma unroll
            for (int j = 0; j < TN; j++) rb[j] = Bs[k][tx*TN + j];
            #pragma unroll
            for (int i = 0; i < TM; i++)
                #pragma unroll
                for (int j = 0; j < TN; j++)
                    acc[i][j] = fmaf(ra[i], rb[j], acc[i][j]);
        }
        __syncthreads();
    }
    #pragma unroll
    for (int i = 0; i < TM; i++) {
        int gm = row0 + ty*TM + i;
        if (gm >= M) continue;
        #pragma unroll
        for (int j = 0; j < TN; j++) {
            int gn = col0 + tx*TN + j;
            if (gn >= N) continue;
            float v = acc[i][j];
            if (bias) v += bias[gn];
            if (relu) v = fmaxf(v, 0.f);
            C[(size_t)gm*N + gn] = v;
        }
    }
}

// ---------------------------------------------------------------------------
// Max-aggregate over the 8 neighbors; write to x buffer and/or xcat slice
// ---------------------------------------------------------------------------
__global__ void max_agg_kernel(const float* __restrict__ Msg, int Cout,
                               float* __restrict__ xout,
                               float* __restrict__ xcat, int cat_off)
{
    int t = blockIdx.x * blockDim.x + threadIdx.x;
    int total = BATCH*NPTS*Cout;
    if (t >= total) return;
    int c = t % Cout;
    int p = t / Cout;
    float v = -FLT_MAX;
    #pragma unroll
    for (int k = 0; k < KNN; k++)
        v = fmaxf(v, Msg[((size_t)p*KNN + k)*Cout + c]);
    if (xout) xout[(size_t)p*Cout + c] = v;
    xcat[(size_t)p*672 + cat_off + c] = v;
}

// ---------------------------------------------------------------------------
// Global max pool over N: g[b,c] = max_n sf[b,n,c]
// ---------------------------------------------------------------------------
__global__ void gpool_kernel(const float* __restrict__ sf, float* __restrict__ g)
{
    int b = blockIdx.x, c = threadIdx.x;   // 128 threads
    float v = -FLT_MAX;
    for (int n = 0; n < NPTS; n++)
        v = fmaxf(v, sf[(((size_t)b*NPTS) + n)*128 + c]);
    g[b*128 + c] = v;
}

// ---------------------------------------------------------------------------
// hg[b,c] = g[b] @ ec_w1[256:384] + ec_b1
// ---------------------------------------------------------------------------
__global__ void hg_kernel(const float* __restrict__ g, const float* __restrict__ w,
                          const float* __restrict__ b1, float* __restrict__ hg)
{
    int b = blockIdx.x, c = threadIdx.x;   // 128 threads
    float acc = b1[c];
    for (int k = 0; k < 128; k++)
        acc = fmaf(g[b*128 + k], w[k*128 + c], acc);
    hg[b*128 + c] = acc;
}

// ---------------------------------------------------------------------------
// Pair kernel: 32x32 pair tiles; hidden = relu(hi[i]+hj[j]+hg); mlp = hidden.w2+b2
// out[b*P + p] = sigmoid(mlp);  out[B*P + b*P + p] = mlp
// ---------------------------------------------------------------------------
__global__ void pair_kernel(const float* __restrict__ hi, const float* __restrict__ hj,
                            const float* __restrict__ hg, const float* __restrict__ w2,
                            const float* __restrict__ b2p, float* __restrict__ out)
{
    const int b  = blockIdx.z;
    const int ib = blockIdx.y;
    const int jb = blockIdx.x;
    if (jb*32 + 31 <= ib*32) return;   // entire tile has j <= i

    __shared__ float shi[32*129];
    __shared__ float shj[32*129];
    __shared__ float shg[128];
    __shared__ float sw2[128];

    int tid = threadIdx.x;   // 1024 threads
    for (int t = tid; t < 32*128; t += 1024) {
        int r = t / 128, c = t % 128;
        int gi = ib*32 + r;
        int gj = jb*32 + r;
        shi[r*129 + c] = (gi < NPTS) ? hi[(((size_t)b*NPTS) + gi)*128 + c] : 0.f;
        shj[r*129 + c] = (gj < NPTS) ? hj[(((size_t)b*NPTS) + gj)*128 + c] : 0.f;
    }
    if (tid < 128) { shg[tid] = hg[b*128 + tid]; sw2[tid] = w2[tid]; }
    __syncthreads();

    int ti = tid >> 5, tj = tid & 31;
    int i = ib*32 + ti, j = jb*32 + tj;
    if (i < NPTS && j < NPTS && i < j) {
        float acc = 0.f;
        #pragma unroll
        for (int c = 0; c < 128; c++) {
            float v = shi[ti*129 + c] + shj[tj*129 + c] + shg[c];
            v = fmaxf(v, 0.f);
            acc = fmaf(v, sw2[c], acc);
        }
        acc += b2p[0];
        int p = i*NPTS - (i*(i+1))/2 + (j - i - 1);
        out[(size_t)b*NPAIR + p] = 1.f / (1.f + expf(-acc));
        out[(size_t)BATCH*NPAIR + (size_t)b*NPAIR + p] = acc;
    }
}

// ---------------------------------------------------------------------------
// Launch
// ---------------------------------------------------------------------------
static inline void run_sgemm(const float* A, const float* W, const float* bias,
                             float* C, int M, int N, int K, int relu)
{
    dim3 grid((N + 63)/64, (M + 63)/64);
    sgemm_kernel<<<grid, 256>>>(A, W, bias, C, M, N, K, relu);
}

extern "C" void kernel_launch(void* const* d_in, const int* in_sizes, int n_in,
                              void* d_out, int out_size)
{
    const float* pos   = (const float*)d_in[0];
    const float* c1_w1 = (const float*)d_in[1];
    const float* c1_b1 = (const float*)d_in[2];
    const float* c1_w2 = (const float*)d_in[3];
    const float* c1_b2 = (const float*)d_in[4];
    const float* c2_w1 = (const float*)d_in[5];
    const float* c2_b1 = (const float*)d_in[6];
    const float* c2_w2 = (const float*)d_in[7];
    const float* c2_b2 = (const float*)d_in[8];
    const float* c3_w1 = (const float*)d_in[9];
    const float* c3_b1 = (const float*)d_in[10];
    const float* c3_w2 = (const float*)d_in[11];
    const float* c3_b2 = (const float*)d_in[12];
    const float* sm_w1 = (const float*)d_in[13];
    const float* sm_b1 = (const float*)d_in[14];
    const float* sm_w2 = (const float*)d_in[15];
    const float* sm_b2 = (const float*)d_in[16];
    const float* ec_w1 = (const float*)d_in[17];
    const float* ec_b1 = (const float*)d_in[18];
    const float* ec_w2 = (const float*)d_in[19];
    const float* ec_b2 = (const float*)d_in[20];

    float* out = (float*)d_out;

    // resolve device scratch pointers
    int*   knn;  cudaGetSymbolAddress((void**)&knn,  g_knn);
    float* E;    cudaGetSymbolAddress((void**)&E,    g_E);
    float* H;    cudaGetSymbolAddress((void**)&H,    g_H);
    float* Msg;  cudaGetSymbolAddress((void**)&Msg,  g_Msg);
    float* x1;   cudaGetSymbolAddress((void**)&x1,   g_x1);
    float* x2;   cudaGetSymbolAddress((void**)&x2,   g_x2);
    float* xcat; cudaGetSymbolAddress((void**)&xcat, g_xcat);
    float* sf;   cudaGetSymbolAddress((void**)&sf,   g_sf);
    float* hi;   cudaGetSymbolAddress((void**)&hi,   g_hi);
    float* hj;   cudaGetSymbolAddress((void**)&hj,   g_hj);
    float* gbuf; cudaGetSymbolAddress((void**)&gbuf, g_g);
    float* hg;   cudaGetSymbolAddress((void**)&hg,   g_hg);

    const int ROWS = BATCH*NPTS*KNN;   // 16000 edge rows
    dim3 knn_grid(NPTS, BATCH);

    // ---- EdgeConv 1: pos (C=3) -> x1 (32) ----
    knn_kernel<3><<<knn_grid, 128>>>(pos, knn);
    {
        int all = BATCH*NPTS*KNN*3;
        build_edges_kernel<<<(all + 255)/256, 256>>>(pos, knn, 3, E);
    }
    run_sgemm(E, c1_w1, c1_b1, H,   ROWS, 16, 6,  1);
    run_sgemm(H, c1_w2, c1_b2, Msg, ROWS, 32, 16, 0);
    {
        int all = BATCH*NPTS*32;
        max_agg_kernel<<<(all + 255)/256, 256>>>(Msg, 32, x1, xcat, 0);
    }

    // ---- EdgeConv 2: x1 (C=32) -> x2 (128) ----
    knn_kernel<32><<<knn_grid, 128>>>(x1, knn);
    {
        int all = BATCH*NPTS*KNN*32;
        build_edges_kernel<<<(all + 255)/256, 256>>>(x1, knn, 32, E);
    }
    run_sgemm(E, c2_w1, c2_b1, H,   ROWS, 64,  64, 1);
    run_sgemm(H, c2_w2, c2_b2, Msg, ROWS, 128, 64, 0);
    {
        int all = BATCH*NPTS*128;
        max_agg_kernel<<<(all + 255)/256, 256>>>(Msg, 128, x2, xcat, 32);
    }

    // ---- EdgeConv 3: x2 (C=128) -> x3 (512) ----
    knn_kernel<128><<<knn_grid, 128>>>(x2, knn);
    {
        int all = BATCH*NPTS*KNN*128;
        build_edges_kernel<<<(all + 255)/256, 256>>>(x2, knn, 128, E);
    }
    run_sgemm(E, c3_w1, c3_b1, H,   ROWS, 256, 256, 1);
    run_sgemm(H, c3_w2, c3_b2, Msg, ROWS, 512, 256, 0);
    {
        int all = BATCH*NPTS*512;
        max_agg_kernel<<<(all + 255)/256, 256>>>(Msg, 512, nullptr, xcat, 160);
    }

    // ---- shared MLP: xcat[2000,672] -> 256 (relu) -> sf[2000,128] ----
    run_sgemm(xcat, sm_w1, sm_b1, H,  BATCH*NPTS, 256, 672, 1);
    run_sgemm(H,    sm_w2, sm_b2, sf, BATCH*NPTS, 128, 256, 0);

    // ---- global pool + edge classifier pieces ----
    gpool_kernel<<<BATCH, 128>>>(sf, gbuf);
    run_sgemm(sf, ec_w1,              nullptr, hi, BATCH*NPTS, 128, 128, 0);
    run_sgemm(sf, ec_w1 + 128*128,    nullptr, hj, BATCH*NPTS, 128, 128, 0);
    hg_kernel<<<BATCH, 128>>>(gbuf, ec_w1 + 256*128, ec_b1, hg);

    // ---- all-pairs classifier ----
    {
        dim3 grid((NPTS + 31)/32, (NPTS + 31)/32, BATCH);
        pair_kernel<<<grid, 1024>>>(hi, hj, hg, ec_w2, ec_b2, out);
    }
}

// round 2
// speedup vs baseline: 1.0371x; 1.0371x over previous
#include <cuda_runtime.h>
#include <cuda_bf16.h>
#include <math.h>
#include <float.h>

// ---------------------------------------------------------------------------
// Problem shape (fixed by setup_inputs): B=2, N=1000, K=8 neighbors
// ---------------------------------------------------------------------------
#define BATCH 2
#define NPTS  1000
#define KNN   8
#define NPAIR ((NPTS*(NPTS-1))/2)   // 499500

// ---------------------------------------------------------------------------
// Static scratch (no allocations allowed)
// ---------------------------------------------------------------------------
__device__ int   g_knn [BATCH*NPTS*KNN];
__device__ float g_E   [BATCH*NPTS*KNN*256];   // edge features, max 2C=256
__device__ float g_H   [BATCH*NPTS*KNN*256];   // hidden,      max 256
__device__ float g_Msg [BATCH*NPTS*KNN*512];   // messages,    max 512
__device__ float g_x1  [BATCH*NPTS*32];
__device__ float g_x2  [BATCH*NPTS*128];
__device__ float g_xcat[BATCH*NPTS*672];
__device__ float g_sf  [BATCH*NPTS*128];
__device__ float g_hi  [BATCH*NPTS*128];
__device__ float g_hj  [BATCH*NPTS*128];
__device__ float g_g   [BATCH*128];
__device__ float g_hg  [BATCH*128];

// ---------------------------------------------------------------------------
// kNN: per (b,n) block computes d2 to all m, keeps 8 smallest (ties -> lower idx)
// IDENTICAL math to R1 (graph stability: x1/x2 feed the next kNN stage).
// ---------------------------------------------------------------------------
template<int C>
__global__ void knn_kernel(const float* __restrict__ x, int* __restrict__ knn)
{
    const int b = blockIdx.y;
    const int n = blockIdx.x;
    const int tid = threadIdx.x;
    const int T = blockDim.x;   // 128
    const float* xb = x + (size_t)b * NPTS * C;

    __shared__ float xq[C];
    __shared__ float sd[128*8];
    __shared__ int   si[128*8];

    for (int c = tid; c < C; c += T) xq[c] = xb[(size_t)n*C + c];
    __syncthreads();

    float sqn = 0.f;
    #pragma unroll
    for (int c = 0; c < C; c++) sqn = fmaf(xq[c], xq[c], sqn);

    float bd[8]; int bi[8];
    #pragma unroll
    for (int k = 0; k < 8; k++) { bd[k] = FLT_MAX; bi[k] = 0x7FFFFFFF; }

    for (int m = tid; m < NPTS; m += T) {
        const float* xm = xb + (size_t)m * C;
        float dot = 0.f, sqm = 0.f;
        #pragma unroll
        for (int c = 0; c < C; c++) {
            float v = xm[c];
            dot = fmaf(xq[c], v, dot);
            sqm = fmaf(v, v, sqm);
        }
        float d = sqn + sqm - 2.f * dot;
        if (d < bd[7] || (d == bd[7] && m < bi[7])) {
            int p = 7;
            #pragma unroll
            for (int it = 0; it < 7; it++) {
                if (p > 0 && (d < bd[p-1] || (d == bd[p-1] && m < bi[p-1]))) {
                    bd[p] = bd[p-1]; bi[p] = bi[p-1]; p--;
                }
            }
            bd[p] = d; bi[p] = m;
        }
    }
    #pragma unroll
    for (int k = 0; k < 8; k++) { sd[tid*8+k] = bd[k]; si[tid*8+k] = bi[k]; }

    for (int s = T/2; s >= 1; s >>= 1) {
        __syncthreads();
        if (tid < s) {
            float* Ad = &sd[tid*8];        int* Ai = &si[tid*8];
            float* Bd = &sd[(tid+s)*8];    int* Bi = &si[(tid+s)*8];
            float od[8]; int oi[8];
            int a = 0, c2 = 0;
            #pragma unroll
            for (int o = 0; o < 8; o++) {
                bool ta = (Ad[a] < Bd[c2]) || (Ad[a] == Bd[c2] && Ai[a] < Bi[c2]);
                if (ta) { od[o] = Ad[a]; oi[o] = Ai[a]; a++; }
                else    { od[o] = Bd[c2]; oi[o] = Bi[c2]; c2++; }
            }
            #pragma unroll
            for (int o = 0; o < 8; o++) { Ad[o] = od[o]; Ai[o] = oi[o]; }
        }
    }
    __syncthreads();
    if (tid < 8) knn[((size_t)b*NPTS + n)*8 + tid] = si[tid];
}

// ---------------------------------------------------------------------------
// Build edge features: E[row] = [x_i , x_j - x_i], row = (b,n,k)
// ---------------------------------------------------------------------------
__global__ void build_edges_kernel(const float* __restrict__ x,
                                   const int* __restrict__ knn,
                                   int C, float* __restrict__ E)
{
    int t = blockIdx.x * blockDim.x + threadIdx.x;
    int all = BATCH*NPTS*KNN*C;
    if (t >= all) return;
    int c = t % C;
    int r = t / C;
    int n = (r / KNN) % NPTS;
    int b = r / (KNN*NPTS);
    int j = knn[r];
    float xi = x[(((size_t)b*NPTS) + n)*C + c];
    float xj = x[(((size_t)b*NPTS) + j)*C + c];
    E[(size_t)r*2*C + c]     = xi;
    E[(size_t)r*2*C + C + c] = xj - xi;
}

// ---------------------------------------------------------------------------
// Fast SGEMM: C[M,N] = act(A[M,K] @ W[K,N] + bias)
// 128x128 tile, BK=16, 256 threads, 8x8 micro-tile, float4 loads.
// Requires K % 16 == 0 and N % 4 == 0.
// ---------------------------------------------------------------------------
__global__ void __launch_bounds__(256, 2)
sgemm128_kernel(const float* __restrict__ A,
                const float* __restrict__ W,
                const float* __restrict__ bias,
                float* __restrict__ C,
                int M, int N, int K, int relu)
{
    const int BM = 128, BN = 128, BK = 16;
    __shared__ float As[BK][BM];   // 8 KB
    __shared__ float Bs[BK][BN];   // 8 KB

    const int tid = threadIdx.x;
    const int tx = tid & 15;       // 0..15 -> 8 cols each
    const int ty = tid >> 4;       // 0..15 -> 8 rows each
    const int row0 = blockIdx.y * BM;
    const int col0 = blockIdx.x * BN;

    float acc[8][8];
    #pragma unroll
    for (int i = 0; i < 8; i++)
        #pragma unroll
        for (int j = 0; j < 8; j++) acc[i][j] = 0.f;

    for (int k0 = 0; k0 < K; k0 += BK) {
        // ---- load A tile (BM x BK), float4 along K, store transposed ----
        #pragma unroll
        for (int t = 0; t < 2; t++) {
            int v  = tid + t * 256;          // 0..511
            int m  = v >> 2;                 // 0..127
            int kq = (v & 3) * 4;            // 0,4,8,12
            int gm = row0 + m;
            float4 a4 = make_float4(0.f, 0.f, 0.f, 0.f);
            if (gm < M)
                a4 = *reinterpret_cast<const float4*>(&A[(size_t)gm * K + k0 + kq]);
            As[kq + 0][m] = a4.x;
            As[kq + 1][m] = a4.y;
            As[kq + 2][m] = a4.z;
            As[kq + 3][m] = a4.w;
        }
        // ---- load B tile (BK x BN), float4 along N ----
        #pragma unroll
        for (int t = 0; t < 2; t++) {
            int v  = tid + t * 256;          // 0..511
            int n4 = (v & 31) * 4;           // 0..124
            int kk = v >> 5;                 // 0..15
            int gn = col0 + n4;
            float4 b4 = make_float4(0.f, 0.f, 0.f, 0.f);
            if (gn < N)
                b4 = *reinterpret_cast<const float4*>(&W[(size_t)(k0 + kk) * N + gn]);
            *reinterpret_cast<float4*>(&Bs[kk][n4]) = b4;
        }
        __syncthreads();

        #pragma unroll
        for (int kk = 0; kk < BK; kk++) {
            float ra[8], rb[8];
            *reinterpret_cast<float4*>(&ra[0]) = *reinterpret_cast<const float4*>(&As[kk][ty*8]);
            *reinterpret_cast<float4*>(&ra[4]) = *reinterpret_cast<const float4*>(&As[kk][ty*8+4]);
            *reinterpret_cast<float4*>(&rb[0]) = *reinterpret_cast<const float4*>(&Bs[kk][tx*8]);
            *reinterpret_cast<float4*>(&rb[4]) = *reinterpret_cast<const float4*>(&Bs[kk][tx*8+4]);
            #pragma unroll
            for (int i = 0; i < 8; i++)
                #pragma unroll
                for (int j = 0; j < 8; j++)
                    acc[i][j] = fmaf(ra[i], rb[j], acc[i][j]);
        }
        __syncthreads();
    }

    // ---- epilogue: bias + relu, float4 stores ----
    float bvals[8];
    #pragma unroll
    for (int j = 0; j < 8; j++) {
        int gn = col0 + tx*8 + j;
        bvals[j] = (bias && gn < N) ? bias[gn] : 0.f;
    }
    #pragma unroll
    for (int i = 0; i < 8; i++) {
        int gm = row0 + ty*8 + i;
        if (gm >= M) continue;
        #pragma unroll
        for (int j = 0; j < 8; j++) {
            int gn = col0 + tx*8 + j;
            if (gn >= N) continue;
            float v = acc[i][j] + bvals[j];
            if (relu) v = fmaxf(v, 0.f);
            C[(size_t)gm * N + gn] = v;
        }
    }
}

// ---------------------------------------------------------------------------
// Naive tiled SGEMM (kept for tiny K=6/16 layers)
// ---------------------------------------------------------------------------
__global__ void sgemm_kernel(const float* __restrict__ A,
                             const float* __restrict__ W,
                             const float* __restrict__ bias,
                             float* __restrict__ C,
                             int M, int N, int K, int relu)
{
    const int BM = 64, BN = 64, BK = 8, TM = 4, TN = 4;
    __shared__ float As[BK][BM];
    __shared__ float Bs[BK][BN];

    int tid = threadIdx.x;
    int tx = tid % 16, ty = tid / 16;
    int row0 = blockIdx.y * BM;
    int col0 = blockIdx.x * BN;

    float acc[TM][TN];
    #pragma unroll
    for (int i = 0; i < TM; i++)
        #pragma unroll
        for (int j = 0; j < TN; j++) acc[i][j] = 0.f;

    for (int k0 = 0; k0 < K; k0 += BK) {
        #pragma unroll
        for (int i = tid; i < BM*BK; i += 256) {
            int m = i / BK, k = i % BK;
            int gm = row0 + m, gk = k0 + k;
            As[k][m] = (gm < M && gk < K) ? A[(size_t)gm*K + gk] : 0.f;
        }
        #pragma unroll
        for (int i = tid; i < BK*BN; i += 256) {
            int k = i / BN, n = i % BN;
            int gk = k0 + k, gn = col0 + n;
            Bs[k][n] = (gk < K && gn < N) ? W[(size_t)gk*N + gn] : 0.f;
        }
        __syncthreads();
        #pragma unroll
        for (int k = 0; k < BK; k++) {
            float ra[TM], rb[TN];
            #pragma unroll
            for (int i = 0; i < TM; i++) ra[i] = As[k][ty*TM + i];
            #pragma unroll
            for (int j = 0; j < TN; j++) rb[j] = Bs[k][tx*TN + j];
            #pragma unroll
            for (int i = 0; i < TM; i++)
                #pragma unroll
                for (int j = 0; j < TN; j++)
                    acc[i][j] = fmaf(ra[i], rb[j], acc[i][j]);
        }
        __syncthreads();
    }
    #pragma unroll
    for (int i = 0; i < TM; i++) {
        int gm = row0 + ty*TM + i;
        if (gm >= M) continue;
        #pragma unroll
        for (int j = 0; j < TN; j++) {
            int gn = col0 + tx*TN + j;
            if (gn >= N) continue;
            float v = acc[i][j];
            if (bias) v += bias[gn];
            if (relu) v = fmaxf(v, 0.f);
            C[(size_t)gm*N + gn] = v;
        }
    }
}

// ---------------------------------------------------------------------------
// Max-aggregate over the 8 neighbors; write to x buffer and/or xcat slice
// ---------------------------------------------------------------------------
__global__ void max_agg_kernel(const float* __restrict__ Msg, int Cout,
                               float* __restrict__ xout,
                               float* __restrict__ xcat, int cat_off)
{
    int t = blockIdx.x * blockDim.x + threadIdx.x;
    int total = BATCH*NPTS*Cout;
    if (t >= total) return;
    int c = t % Cout;
    int p = t / Cout;
    float v = -FLT_MAX;
    #pragma unroll
    for (int k = 0; k < KNN; k++)
        v = fmaxf(v, Msg[((size_t)p*KNN + k)*Cout + c]);
    if (xout) xout[(size_t)p*Cout + c] = v;
    xcat[(size_t)p*672 + cat_off + c] = v;
}

// ---------------------------------------------------------------------------
// Global max pool over N: g[b,c] = max_n sf[b,n,c]
// ---------------------------------------------------------------------------
__global__ void gpool_kernel(const float* __restrict__ sf, float* __restrict__ g)
{
    int b = blockIdx.x, c = threadIdx.x;   // 128 threads
    float v = -FLT_MAX;
    for (int n = 0; n < NPTS; n++)
        v = fmaxf(v, sf[(((size_t)b*NPTS) + n)*128 + c]);
    g[b*128 + c] = v;
}

// ---------------------------------------------------------------------------
// hg[b,c] = g[b] @ ec_w1[256:384] + ec_b1
// ---------------------------------------------------------------------------
__global__ void hg_kernel(const float* __restrict__ g, const float* __restrict__ w,
                          const float* __restrict__ b1, float* __restrict__ hg)
{
    int b = blockIdx.x, c = threadIdx.x;   // 128 threads
    float acc = b1[c];
    for (int k = 0; k < 128; k++)
        acc = fmaf(g[b*128 + k], w[k*128 + c], acc);
    hg[b*128 + c] = acc;
}

// ---------------------------------------------------------------------------
// Pair kernel: 32x32 pair tiles; hidden = relu(hi[i]+hj[j]+hg); mlp = hidden.w2+b2
// ---------------------------------------------------------------------------
__global__ void pair_kernel(const float* __restrict__ hi, const float* __restrict__ hj,
                            const float* __restrict__ hg, const float* __restrict__ w2,
                            const float* __restrict__ b2p, float* __restrict__ out)
{
    const int b  = blockIdx.z;
    const int ib = blockIdx.y;
    const int jb = blockIdx.x;
    if (jb*32 + 31 <= ib*32) return;   // entire tile has j <= i

    __shared__ float shi[32*129];
    __shared__ float shj[32*129];
    __shared__ float shg[128];
    __shared__ float sw2[128];

    int tid = threadIdx.x;   // 1024 threads
    for (int t = tid; t < 32*128; t += 1024) {
        int r = t / 128, c = t % 128;
        int gi = ib*32 + r;
        int gj = jb*32 + r;
        shi[r*129 + c] = (gi < NPTS) ? hi[(((size_t)b*NPTS) + gi)*128 + c] : 0.f;
        shj[r*129 + c] = (gj < NPTS) ? hj[(((size_t)b*NPTS) + gj)*128 + c] : 0.f;
    }
    if (tid < 128) { shg[tid] = hg[b*128 + tid]; sw2[tid] = w2[tid]; }
    __syncthreads();

    int ti = tid >> 5, tj = tid & 31;
    int i = ib*32 + ti, j = jb*32 + tj;
    if (i < NPTS && j < NPTS && i < j) {
        float acc = 0.f;
        #pragma unroll
        for (int c = 0; c < 128; c++) {
            float v = shi[ti*129 + c] + shj[tj*129 + c] + shg[c];
            v = fmaxf(v, 0.f);
            acc = fmaf(v, sw2[c], acc);
        }
        acc += b2p[0];
        int p = i*NPTS - (i*(i+1))/2 + (j - i - 1);
        out[(size_t)b*NPAIR + p] = 1.f / (1.f + expf(-acc));
        out[(size_t)BATCH*NPAIR + (size_t)b*NPAIR + p] = acc;
    }
}

// ---------------------------------------------------------------------------
// Launch helpers
// ---------------------------------------------------------------------------
static inline void run_sgemm_small(const float* A, const float* W, const float* bias,
                                   float* C, int M, int N, int K, int relu)
{
    dim3 grid((N + 63)/64, (M + 63)/64);
    sgemm_kernel<<<grid, 256>>>(A, W, bias, C, M, N, K, relu);
}

static inline void run_sgemm_fast(const float* A, const float* W, const float* bias,
                                  float* C, int M, int N, int K, int relu)
{
    // requires K % 16 == 0 && N % 4 == 0
    dim3 grid((N + 127)/128, (M + 127)/128);
    sgemm128_kernel<<<grid, 256>>>(A, W, bias, C, M, N, K, relu);
}

extern "C" void kernel_launch(void* const* d_in, const int* in_sizes, int n_in,
                              void* d_out, int out_size)
{
    const float* pos   = (const float*)d_in[0];
    const float* c1_w1 = (const float*)d_in[1];
    const float* c1_b1 = (const float*)d_in[2];
    const float* c1_w2 = (const float*)d_in[3];
    const float* c1_b2 = (const float*)d_in[4];
    const float* c2_w1 = (const float*)d_in[5];
    const float* c2_b1 = (const float*)d_in[6];
    const float* c2_w2 = (const float*)d_in[7];
    const float* c2_b2 = (const float*)d_in[8];
    const float* c3_w1 = (const float*)d_in[9];
    const float* c3_b1 = (const float*)d_in[10];
    const float* c3_w2 = (const float*)d_in[11];
    const float* c3_b2 = (const float*)d_in[12];
    const float* sm_w1 = (const float*)d_in[13];
    const float* sm_b1 = (const float*)d_in[14];
    const float* sm_w2 = (const float*)d_in[15];
    const float* sm_b2 = (const float*)d_in[16];
    const float* ec_w1 = (const float*)d_in[17];
    const float* ec_b1 = (const float*)d_in[18];
    const float* ec_w2 = (const float*)d_in[19];
    const float* ec_b2 = (const float*)d_in[20];

    float* out = (float*)d_out;

    int*   knn;  cudaGetSymbolAddress((void**)&knn,  g_knn);
    float* E;    cudaGetSymbolAddress((void**)&E,    g_E);
    float* H;    cudaGetSymbolAddress((void**)&H,    g_H);
    float* Msg;  cudaGetSymbolAddress((void**)&Msg,  g_Msg);
    float* x1;   cudaGetSymbolAddress((void**)&x1,   g_x1);
    float* x2;   cudaGetSymbolAddress((void**)&x2,   g_x2);
    float* xcat; cudaGetSymbolAddress((void**)&xcat, g_xcat);
    float* sf;   cudaGetSymbolAddress((void**)&sf,   g_sf);
    float* hi;   cudaGetSymbolAddress((void**)&hi,   g_hi);
    float* hj;   cudaGetSymbolAddress((void**)&hj,   g_hj);
    float* gbuf; cudaGetSymbolAddress((void**)&gbuf, g_g);
    float* hg;   cudaGetSymbolAddress((void**)&hg,   g_hg);

    const int ROWS = BATCH*NPTS*KNN;   // 16000 edge rows
    dim3 knn_grid(NPTS, BATCH);

    // ---- EdgeConv 1: pos (C=3) -> x1 (32) ----
    knn_kernel<3><<<knn_grid, 128>>>(pos, knn);
    {
        int all = BATCH*NPTS*KNN*3;
        build_edges_kernel<<<(all + 255)/256, 256>>>(pos, knn, 3, E);
    }
    run_sgemm_small(E, c1_w1, c1_b1, H,   ROWS, 16, 6,  1);
    run_sgemm_fast (H, c1_w2, c1_b2, Msg, ROWS, 32, 16, 0);
    {
        int all = BATCH*NPTS*32;
        max_agg_kernel<<<(all + 255)/256, 256>>>(Msg, 32, x1, xcat, 0);
    }

    // ---- EdgeConv 2: x1 (C=32) -> x2 (128) ----
    knn_kernel<32><<<knn_grid, 128>>>(x1, knn);
    {
        int all = BATCH*NPTS*KNN*32;
        build_edges_kernel<<<(all + 255)/256, 256>>>(x1, knn, 32, E);
    }
    run_sgemm_fast(E, c2_w1, c2_b1, H,   ROWS, 64,  64, 1);
    run_sgemm_fast(H, c2_w2, c2_b2, Msg, ROWS, 128, 64, 0);
    {
        int all = BATCH*NPTS*128;
        max_agg_kernel<<<(all + 255)/256, 256>>>(Msg, 128, x2, xcat, 32);
    }

    // ---- EdgeConv 3: x2 (C=128) -> x3 (512) ----
    knn_kernel<128><<<knn_grid, 128>>>(x2, knn);
    {
        int all = BATCH*NPTS*KNN*128;
        build_edges_kernel<<<(all + 255)/256, 256>>>(x2, knn, 128, E);
    }
    run_sgemm_fast(E, c3_w1, c3_b1, H,   ROWS, 256, 256, 1);
    run_sgemm_fast(H, c3_w2, c3_b2, Msg, ROWS, 512, 256, 0);
    {
        int all = BATCH*NPTS*512;
        max_agg_kernel<<<(all + 255)/256, 256>>>(Msg, 512, nullptr, xcat, 160);
    }

    // ---- shared MLP: xcat[2000,672] -> 256 (relu) -> sf[2000,128] ----
    run_sgemm_fast(xcat, sm_w1, sm_b1, H,  BATCH*NPTS, 256, 672, 1);
    run_sgemm_fast(H,    sm_w2, sm_b2, sf, BATCH*NPTS, 128, 256, 0);

    // ---- global pool + edge classifier pieces ----
    gpool_kernel<<<BATCH, 128>>>(sf, gbuf);
    run_sgemm_fast(sf, ec_w1,           nullptr, hi, BATCH*NPTS, 128, 128, 0);
    run_sgemm_fast(sf, ec_w1 + 128*128, nullptr, hj, BATCH*NPTS, 128, 128, 0);
    hg_kernel<<<BATCH, 128>>>(gbuf, ec_w1 + 256*128, ec_b1, hg);

    // ---- all-pairs classifier ----
    {
        dim3 grid((NPTS + 31)/32, (NPTS + 31)/32, BATCH);
        pair_kernel<<<grid, 1024>>>(hi, hj, hg, ec_w2, ec_b2, out);
    }
}

// round 3
// speedup vs baseline: 2.9820x; 2.8753x over previous
#include <cuda_runtime.h>
#include <cuda_bf16.h>
#include <math.h>
#include <float.h>

#define BATCH 2
#define NPTS  1000
#define KNN   8
#define NPAIR ((NPTS*(NPTS-1))/2)   // 499500

// ---------------------------------------------------------------------------
// Static scratch
// ---------------------------------------------------------------------------
__device__ int   g_knn [BATCH*NPTS*KNN];
__device__ float g_sq  [BATCH*NPTS];
__device__ float g_d2  [BATCH*NPTS*NPTS];      // 8 MB distance matrix
__device__ float g_E   [BATCH*NPTS*KNN*256];
__device__ float g_H   [BATCH*NPTS*KNN*256];
__device__ float g_Msg [BATCH*NPTS*KNN*512];
__device__ float g_x1  [BATCH*NPTS*32];
__device__ float g_x2  [BATCH*NPTS*128];
__device__ float g_xcat[BATCH*NPTS*672];
__device__ float g_sf  [BATCH*NPTS*128];
__device__ float g_hi  [BATCH*NPTS*128];
__device__ float g_hj  [BATCH*NPTS*128];
__device__ float g_g   [BATCH*128];
__device__ float g_hg  [BATCH*128];

// ---------------------------------------------------------------------------
// sq[b,n] = sum_c x^2   (tiny)
// ---------------------------------------------------------------------------
template<int C>
__global__ void sq_kernel(const float* __restrict__ x, float* __restrict__ sq)
{
    int t = blockIdx.x * blockDim.x + threadIdx.x;
    if (t >= BATCH*NPTS) return;
    const float* row = x + (size_t)t * C;
    float s = 0.f;
    #pragma unroll
    for (int c = 0; c < C; c++) s = fmaf(row[c], row[c], s);
    sq[t] = s;
}

// ---------------------------------------------------------------------------
// Pairwise distance tile kernel: d2[b,n,m] = sq[n] + sq[m] - 2*dot(x_n, x_m)
// 64x64 tiles, BK=32, 256 threads, 4x4 micro-tile, coalesced loads.
// ---------------------------------------------------------------------------
template<int C>
__global__ void __launch_bounds__(256)
dist_kernel(const float* __restrict__ x, const float* __restrict__ sq,
            float* __restrict__ d2)
{
    const int b  = blockIdx.z;
    const int n0 = blockIdx.y * 64;
    const int m0 = blockIdx.x * 64;
    const float* xb  = x  + (size_t)b * NPTS * C;
    const float* sqb = sq + b * NPTS;

    __shared__ float As[32][68];
    __shared__ float Bs[32][68];

    const int tid = threadIdx.x;
    const int ti = tid >> 4;    // 0..15
    const int tj = tid & 15;    // 0..15

    float acc[4][4];
    #pragma unroll
    for (int i = 0; i < 4; i++)
        #pragma unroll
        for (int j = 0; j < 4; j++) acc[i][j] = 0.f;

    for (int k0 = 0; k0 < C; k0 += 32) {
        #pragma unroll
        for (int v = tid; v < 512; v += 256) {
            int r  = v >> 3;         // 0..63
            int cq = (v & 7) * 4;    // 0..28
            // A side (rows n0+r)
            {
                int row = n0 + r;
                float4 a4 = make_float4(0.f, 0.f, 0.f, 0.f);
                if (row < NPTS) {
                    if ((C & 31) == 0) {
                        a4 = *reinterpret_cast<const float4*>(&xb[(size_t)row*C + k0 + cq]);
                    } else {
                        float tmp[4];
                        #pragma unroll
                        for (int t2 = 0; t2 < 4; t2++) {
                            int k = k0 + cq + t2;
                            tmp[t2] = (k < C) ? xb[(size_t)row*C + k] : 0.f;
                        }
                        a4 = make_float4(tmp[0], tmp[1], tmp[2], tmp[3]);
                    }
                }
                As[cq+0][r] = a4.x; As[cq+1][r] = a4.y;
                As[cq+2][r] = a4.z; As[cq+3][r] = a4.w;
            }
            // B side (rows m0+r)
            {
                int row = m0 + r;
                float4 b4 = make_float4(0.f, 0.f, 0.f, 0.f);
                if (row < NPTS) {
                    if ((C & 31) == 0) {
                        b4 = *reinterpret_cast<const float4*>(&xb[(size_t)row*C + k0 + cq]);
                    } else {
                        float tmp[4];
                        #pragma unroll
                        for (int t2 = 0; t2 < 4; t2++) {
                            int k = k0 + cq + t2;
                            tmp[t2] = (k < C) ? xb[(size_t)row*C + k] : 0.f;
                        }
                        b4 = make_float4(tmp[0], tmp[1], tmp[2], tmp[3]);
                    }
                }
                Bs[cq+0][r] = b4.x; Bs[cq+1][r] = b4.y;
                Bs[cq+2][r] = b4.z; Bs[cq+3][r] = b4.w;
            }
        }
        __syncthreads();
        #pragma unroll
        for (int kk = 0; kk < 32; kk++) {
            float ra[4], rb[4];
            *reinterpret_cast<float4*>(ra) = *reinterpret_cast<const float4*>(&As[kk][ti*4]);
            *reinterpret_cast<float4*>(rb) = *reinterpret_cast<const float4*>(&Bs[kk][tj*4]);
            #pragma unroll
            for (int i = 0; i < 4; i++)
                #pragma unroll
                for (int j = 0; j < 4; j++)
                    acc[i][j] = fmaf(ra[i], rb[j], acc[i][j]);
        }
        __syncthreads();
    }

    const int ni = n0 + ti*4;
    const int mj = m0 + tj*4;
    float sqi[4], sqj[4];
    #pragma unroll
    for (int i = 0; i < 4; i++) sqi[i] = (ni+i < NPTS) ? sqb[ni+i] : 0.f;
    #pragma unroll
    for (int j = 0; j < 4; j++) sqj[j] = (mj+j < NPTS) ? sqb[mj+j] : 0.f;
    #pragma unroll
    for (int i = 0; i < 4; i++) {
        if (ni+i >= NPTS) continue;
        #pragma unroll
        for (int j = 0; j < 4; j++) {
            if (mj+j >= NPTS) continue;
            d2[((size_t)b*NPTS + ni+i)*NPTS + mj+j] = sqi[i] + sqj[j] - 2.f*acc[i][j];
        }
    }
}

// ---------------------------------------------------------------------------
// Top-8 per row of d2 (coalesced scan + sorted merge tree; ties -> lower idx)
// ---------------------------------------------------------------------------
__global__ void topk_kernel(const float* __restrict__ d2, int* __restrict__ knn)
{
    const int b = blockIdx.y;
    const int n = blockIdx.x;
    const int tid = threadIdx.x;   // 128
    const float* row = d2 + ((size_t)b*NPTS + n)*NPTS;

    __shared__ float sd[128*8];
    __shared__ int   si[128*8];

    float bd[8]; int bi[8];
    #pragma unroll
    for (int k = 0; k < 8; k++) { bd[k] = FLT_MAX; bi[k] = 0x7FFFFFFF; }

    for (int m = tid; m < NPTS; m += 128) {
        float d = row[m];
        if (d < bd[7] || (d == bd[7] && m < bi[7])) {
            int p = 7;
            #pragma unroll
            for (int it = 0; it < 7; it++) {
                if (p > 0 && (d < bd[p-1] || (d == bd[p-1] && m < bi[p-1]))) {
                    bd[p] = bd[p-1]; bi[p] = bi[p-1]; p--;
                }
            }
            bd[p] = d; bi[p] = m;
        }
    }
    #pragma unroll
    for (int k = 0; k < 8; k++) { sd[tid*8+k] = bd[k]; si[tid*8+k] = bi[k]; }

    for (int s = 64; s >= 1; s >>= 1) {
        __syncthreads();
        if (tid < s) {
            float* Ad = &sd[tid*8];        int* Ai = &si[tid*8];
            float* Bd = &sd[(tid+s)*8];    int* Bi = &si[(tid+s)*8];
            float od[8]; int oi[8];
            int a = 0, c2 = 0;
            #pragma unroll
            for (int o = 0; o < 8; o++) {
                bool ta = (Ad[a] < Bd[c2]) || (Ad[a] == Bd[c2] && Ai[a] < Bi[c2]);
                if (ta) { od[o] = Ad[a]; oi[o] = Ai[a]; a++; }
                else    { od[o] = Bd[c2]; oi[o] = Bi[c2]; c2++; }
            }
            #pragma unroll
            for (int o = 0; o < 8; o++) { Ad[o] = od[o]; Ai[o] = oi[o]; }
        }
    }
    __syncthreads();
    if (tid < 8) knn[((size_t)b*NPTS + n)*8 + tid] = si[tid];
}

// ---------------------------------------------------------------------------
// Build edge features
// ---------------------------------------------------------------------------
__global__ void build_edges_kernel(const float* __restrict__ x,
                                   const int* __restrict__ knn,
                                   int C, float* __restrict__ E)
{
    int t = blockIdx.x * blockDim.x + threadIdx.x;
    int all = BATCH*NPTS*KNN*C;
    if (t >= all) return;
    int c = t % C;
    int r = t / C;
    int n = (r / KNN) % NPTS;
    int b = r / (KNN*NPTS);
    int j = knn[r];
    float xi = x[(((size_t)b*NPTS) + n)*C + c];
    float xj = x[(((size_t)b*NPTS) + j)*C + c];
    E[(size_t)r*2*C + c]     = xi;
    E[(size_t)r*2*C + C + c] = xj - xi;
}

// ---------------------------------------------------------------------------
// SGEMM 128x128, BK=16, 8x8 micro (big-M GEMMs). K%16==0, N%4==0.
// ---------------------------------------------------------------------------
__global__ void __launch_bounds__(256, 2)
sgemm128_kernel(const float* __restrict__ A, const float* __restrict__ W,
                const float* __restrict__ bias, float* __restrict__ C,
                int M, int N, int K, int relu)
{
    const int BK = 16;
    __shared__ float As[BK][128];
    __shared__ float Bs[BK][128];

    const int tid = threadIdx.x;
    const int tx = tid & 15;
    const int ty = tid >> 4;
    const int row0 = blockIdx.y * 128;
    const int col0 = blockIdx.x * 128;

    float acc[8][8];
    #pragma unroll
    for (int i = 0; i < 8; i++)
        #pragma unroll
        for (int j = 0; j < 8; j++) acc[i][j] = 0.f;

    for (int k0 = 0; k0 < K; k0 += BK) {
        #pragma unroll
        for (int t = 0; t < 2; t++) {
            int v  = tid + t * 256;
            int m  = v >> 2;
            int kq = (v & 3) * 4;
            int gm = row0 + m;
            float4 a4 = make_float4(0.f, 0.f, 0.f, 0.f);
            if (gm < M)
                a4 = *reinterpret_cast<const float4*>(&A[(size_t)gm * K + k0 + kq]);
            As[kq+0][m] = a4.x; As[kq+1][m] = a4.y;
            As[kq+2][m] = a4.z; As[kq+3][m] = a4.w;
        }
        #pragma unroll
        for (int t = 0; t < 2; t++) {
            int v  = tid + t * 256;
            int n4 = (v & 31) * 4;
            int kk = v >> 5;
            int gn = col0 + n4;
            float4 b4 = make_float4(0.f, 0.f, 0.f, 0.f);
            if (gn < N)
                b4 = *reinterpret_cast<const float4*>(&W[(size_t)(k0 + kk) * N + gn]);
            *reinterpret_cast<float4*>(&Bs[kk][n4]) = b4;
        }
        __syncthreads();
        #pragma unroll
        for (int kk = 0; kk < BK; kk++) {
            float ra[8], rb[8];
            *reinterpret_cast<float4*>(&ra[0]) = *reinterpret_cast<const float4*>(&As[kk][ty*8]);
            *reinterpret_cast<float4*>(&ra[4]) = *reinterpret_cast<const float4*>(&As[kk][ty*8+4]);
            *reinterpret_cast<float4*>(&rb[0]) = *reinterpret_cast<const float4*>(&Bs[kk][tx*8]);
            *reinterpret_cast<float4*>(&rb[4]) = *reinterpret_cast<const float4*>(&Bs[kk][tx*8+4]);
            #pragma unroll
            for (int i = 0; i < 8; i++)
                #pragma unroll
                for (int j = 0; j < 8; j++)
                    acc[i][j] = fmaf(ra[i], rb[j], acc[i][j]);
        }
        __syncthreads();
    }

    float bvals[8];
    #pragma unroll
    for (int j = 0; j < 8; j++) {
        int gn = col0 + tx*8 + j;
        bvals[j] = (bias && gn < N) ? bias[gn] : 0.f;
    }
    #pragma unroll
    for (int i = 0; i < 8; i++) {
        int gm = row0 + ty*8 + i;
        if (gm >= M) continue;
        #pragma unroll
        for (int j = 0; j < 8; j++) {
            int gn = col0 + tx*8 + j;
            if (gn >= N) continue;
            float v = acc[i][j] + bvals[j];
            if (relu) v = fmaxf(v, 0.f);
            C[(size_t)gm * N + gn] = v;
        }
    }
}

// ---------------------------------------------------------------------------
// SGEMM 64x64, BK=16, 4x4 micro (small-M GEMMs). K%16==0, N%4==0.
// ---------------------------------------------------------------------------
__global__ void __launch_bounds__(256)
sgemm64_kernel(const float* __restrict__ A, const float* __restrict__ W,
               const float* __restrict__ bias, float* __restrict__ C,
               int M, int N, int K, int relu)
{
    __shared__ float As[16][64];
    __shared__ float Bs[16][64];

    const int tid = threadIdx.x;
    const int tx = tid & 15;
    const int ty = tid >> 4;
    const int row0 = blockIdx.y * 64;
    const int col0 = blockIdx.x * 64;

    float acc[4][4];
    #pragma unroll
    for (int i = 0; i < 4; i++)
        #pragma unroll
        for (int j = 0; j < 4; j++) acc[i][j] = 0.f;

    for (int k0 = 0; k0 < K; k0 += 16) {
        {
            int m  = tid >> 2;        // 0..63
            int kq = (tid & 3) * 4;   // 0,4,8,12
            int gm = row0 + m;
            float4 a4 = make_float4(0.f, 0.f, 0.f, 0.f);
            if (gm < M)
                a4 = *reinterpret_cast<const float4*>(&A[(size_t)gm * K + k0 + kq]);
            As[kq+0][m] = a4.x; As[kq+1][m] = a4.y;
            As[kq+2][m] = a4.z; As[kq+3][m] = a4.w;
        }
        {
            int kk = tid >> 4;        // 0..15
            int n4 = (tid & 15) * 4;  // 0..60
            int gn = col0 + n4;
            float4 b4 = make_float4(0.f, 0.f, 0.f, 0.f);
            if (gn < N)
                b4 = *reinterpret_cast<const float4*>(&W[(size_t)(k0 + kk) * N + gn]);
            *reinterpret_cast<float4*>(&Bs[kk][n4]) = b4;
        }
        __syncthreads();
        #pragma unroll
        for (int kk = 0; kk < 16; kk++) {
            float ra[4], rb[4];
            *reinterpret_cast<float4*>(ra) = *reinterpret_cast<const float4*>(&As[kk][ty*4]);
            *reinterpret_cast<float4*>(rb) = *reinterpret_cast<const float4*>(&Bs[kk][tx*4]);
            #pragma unroll
            for (int i = 0; i < 4; i++)
                #pragma unroll
                for (int j = 0; j < 4; j++)
                    acc[i][j] = fmaf(ra[i], rb[j], acc[i][j]);
        }
        __syncthreads();
    }
    #pragma unroll
    for (int i = 0; i < 4; i++) {
        int gm = row0 + ty*4 + i;
        if (gm >= M) continue;
        #pragma unroll
        for (int j = 0; j < 4; j++) {
            int gn = col0 + tx*4 + j;
            if (gn >= N) continue;
            float v = acc[i][j];
            if (bias) v += bias[gn];
            if (relu) v = fmaxf(v, 0.f);
            C[(size_t)gm * N + gn] = v;
        }
    }
}

// ---------------------------------------------------------------------------
// Naive tiled SGEMM for tiny K (c1a: K=6)
// ---------------------------------------------------------------------------
__global__ void sgemm_kernel(const float* __restrict__ A, const float* __restrict__ W,
                             const float* __restrict__ bias, float* __restrict__ C,
                             int M, int N, int K, int relu)
{
    const int BM = 64, BN = 64, BK = 8, TM = 4, TN = 4;
    __shared__ float As[BK][BM];
    __shared__ float Bs[BK][BN];

    int tid = threadIdx.x;
    int tx = tid % 16, ty = tid / 16;
    int row0 = blockIdx.y * BM;
    int col0 = blockIdx.x * BN;

    float acc[TM][TN];
    #pragma unroll
    for (int i = 0; i < TM; i++)
        #pragma unroll
        for (int j = 0; j < TN; j++) acc[i][j] = 0.f;

    for (int k0 = 0; k0 < K; k0 += BK) {
        for (int i = tid; i < BM*BK; i += 256) {
            int m = i / BK, k = i % BK;
            int gm = row0 + m, gk = k0 + k;
            As[k][m] = (gm < M && gk < K) ? A[(size_t)gm*K + gk] : 0.f;
        }
        for (int i = tid; i < BK*BN; i += 256) {
            int k = i / BN, n = i % BN;
            int gk = k0 + k, gn = col0 + n;
            Bs[k][n] = (gk < K && gn < N) ? W[(size_t)gk*N + gn] : 0.f;
        }
        __syncthreads();
        #pragma unroll
        for (int k = 0; k < BK; k++) {
            float ra[TM], rb[TN];
            #pragma unroll
            for (int i = 0; i < TM; i++) ra[i] = As[k][ty*TM + i];
            #pragma unroll
            for (int j = 0; j < TN; j++) rb[j] = Bs[k][tx*TN + j];
            #pragma unroll
            for (int i = 0; i < TM; i++)
                #pragma unroll
                for (int j = 0; j < TN; j++)
                    acc[i][j] = fmaf(ra[i], rb[j], acc[i][j]);
        }
        __syncthreads();
    }
    #pragma unroll
    for (int i = 0; i < TM; i++) {
        int gm = row0 + ty*TM + i;
        if (gm >= M) continue;
        #pragma unroll
        for (int j = 0; j < TN; j++) {
            int gn = col0 + tx*TN + j;
            if (gn >= N) continue;
            float v = acc[i][j];
            if (bias) v += bias[gn];
            if (relu) v = fmaxf(v, 0.f);
            C[(size_t)gm*N + gn] = v;
        }
    }
}

// ---------------------------------------------------------------------------
// Max-aggregate over 8 neighbors
// ---------------------------------------------------------------------------
__global__ void max_agg_kernel(const float* __restrict__ Msg, int Cout,
                               float* __restrict__ xout,
                               float* __restrict__ xcat, int cat_off)
{
    int t = blockIdx.x * blockDim.x + threadIdx.x;
    int total = BATCH*NPTS*Cout;
    if (t >= total) return;
    int c = t % Cout;
    int p = t / Cout;
    float v = -FLT_MAX;
    #pragma unroll
    for (int k = 0; k < KNN; k++)
        v = fmaxf(v, Msg[((size_t)p*KNN + k)*Cout + c]);
    if (xout) xout[(size_t)p*Cout + c] = v;
    xcat[(size_t)p*672 + cat_off + c] = v;
}

__global__ void gpool_kernel(const float* __restrict__ sf, float* __restrict__ g)
{
    int b = blockIdx.x, c = threadIdx.x;
    float v = -FLT_MAX;
    for (int n = 0; n < NPTS; n++)
        v = fmaxf(v, sf[(((size_t)b*NPTS) + n)*128 + c]);
    g[b*128 + c] = v;
}

__global__ void hg_kernel(const float* __restrict__ g, const float* __restrict__ w,
                          const float* __restrict__ b1, float* __restrict__ hg)
{
    int b = blockIdx.x, c = threadIdx.x;
    float acc = b1[c];
    for (int k = 0; k < 128; k++)
        acc = fmaf(g[b*128 + k], w[k*128 + c], acc);
    hg[b*128 + c] = acc;
}

// ---------------------------------------------------------------------------
// Pair kernel
// ---------------------------------------------------------------------------
__global__ void pair_kernel(const float* __restrict__ hi, const float* __restrict__ hj,
                            const float* __restrict__ hg, const float* __restrict__ w2,
                            const float* __restrict__ b2p, float* __restrict__ out)
{
    const int b  = blockIdx.z;
    const int ib = blockIdx.y;
    const int jb = blockIdx.x;
    if (jb*32 + 31 <= ib*32) return;

    __shared__ float shi[32*129];
    __shared__ float shj[32*129];
    __shared__ float shg[128];
    __shared__ float sw2[128];

    int tid = threadIdx.x;   // 1024
    for (int t = tid; t < 32*128; t += 1024) {
        int r = t / 128, c = t % 128;
        int gi = ib*32 + r;
        int gj = jb*32 + r;
        shi[r*129 + c] = (gi < NPTS) ? hi[(((size_t)b*NPTS) + gi)*128 + c] : 0.f;
        shj[r*129 + c] = (gj < NPTS) ? hj[(((size_t)b*NPTS) + gj)*128 + c] : 0.f;
    }
    if (tid < 128) { shg[tid] = hg[b*128 + tid]; sw2[tid] = w2[tid]; }
    __syncthreads();

    int ti = tid >> 5, tj = tid & 31;
    int i = ib*32 + ti, j = jb*32 + tj;
    if (i < NPTS && j < NPTS && i < j) {
        float acc = 0.f;
        #pragma unroll
        for (int c = 0; c < 128; c++) {
            float v = shi[ti*129 + c] + shj[tj*129 + c] + shg[c];
            v = fmaxf(v, 0.f);
            acc = fmaf(v, sw2[c], acc);
        }
        acc += b2p[0];
        int p = i*NPTS - (i*(i+1))/2 + (j - i - 1);
        out[(size_t)b*NPAIR + p] = 1.f / (1.f + expf(-acc));
        out[(size_t)BATCH*NPAIR + (size_t)b*NPAIR + p] = acc;
    }
}

// ---------------------------------------------------------------------------
// Launch helpers
// ---------------------------------------------------------------------------
static inline void run_sgemm_small(const float* A, const float* W, const float* bias,
                                   float* C, int M, int N, int K, int relu)
{
    dim3 grid((N + 63)/64, (M + 63)/64);
    sgemm_kernel<<<grid, 256>>>(A, W, bias, C, M, N, K, relu);
}
static inline void run_sgemm128(const float* A, const float* W, const float* bias,
                                float* C, int M, int N, int K, int relu)
{
    dim3 grid((N + 127)/128, (M + 127)/128);
    sgemm128_kernel<<<grid, 256>>>(A, W, bias, C, M, N, K, relu);
}
static inline void run_sgemm64(const float* A, const float* W, const float* bias,
                               float* C, int M, int N, int K, int relu)
{
    dim3 grid((N + 63)/64, (M + 63)/64);
    sgemm64_kernel<<<grid, 256>>>(A, W, bias, C, M, N, K, relu);
}

template<int C>
static inline void run_knn(const float* x, float* sqb, float* d2, int* knn)
{
    sq_kernel<C><<<(BATCH*NPTS + 127)/128, 128>>>(x, sqb);
    dim3 dgrid((NPTS + 63)/64, (NPTS + 63)/64, BATCH);
    dist_kernel<C><<<dgrid, 256>>>(x, sqb, d2);
    dim3 tgrid(NPTS, BATCH);
    topk_kernel<<<tgrid, 128>>>(d2, knn);
}

extern "C" void kernel_launch(void* const* d_in, const int* in_sizes, int n_in,
                              void* d_out, int out_size)
{
    const float* pos   = (const float*)d_in[0];
    const float* c1_w1 = (const float*)d_in[1];
    const float* c1_b1 = (const float*)d_in[2];
    const float* c1_w2 = (const float*)d_in[3];
    const float* c1_b2 = (const float*)d_in[4];
    const float* c2_w1 = (const float*)d_in[5];
    const float* c2_b1 = (const float*)d_in[6];
    const float* c2_w2 = (const float*)d_in[7];
    const float* c2_b2 = (const float*)d_in[8];
    const float* c3_w1 = (const float*)d_in[9];
    const float* c3_b1 = (const float*)d_in[10];
    const float* c3_w2 = (const float*)d_in[11];
    const float* c3_b2 = (const float*)d_in[12];
    const float* sm_w1 = (const float*)d_in[13];
    const float* sm_b1 = (const float*)d_in[14];
    const float* sm_w2 = (const float*)d_in[15];
    const float* sm_b2 = (const float*)d_in[16];
    const float* ec_w1 = (const float*)d_in[17];
    const float* ec_b1 = (const float*)d_in[18];
    const float* ec_w2 = (const float*)d_in[19];
    const float* ec_b2 = (const float*)d_in[20];

    float* out = (float*)d_out;

    int*   knn;  cudaGetSymbolAddress((void**)&knn,  g_knn);
    float* sqb;  cudaGetSymbolAddress((void**)&sqb,  g_sq);
    float* d2;   cudaGetSymbolAddress((void**)&d2,   g_d2);
    float* E;    cudaGetSymbolAddress((void**)&E,    g_E);
    float* H;    cudaGetSymbolAddress((void**)&H,    g_H);
    float* Msg;  cudaGetSymbolAddress((void**)&Msg,  g_Msg);
    float* x1;   cudaGetSymbolAddress((void**)&x1,   g_x1);
    float* x2;   cudaGetSymbolAddress((void**)&x2,   g_x2);
    float* xcat; cudaGetSymbolAddress((void**)&xcat, g_xcat);
    float* sf;   cudaGetSymbolAddress((void**)&sf,   g_sf);
    float* hi;   cudaGetSymbolAddress((void**)&hi,   g_hi);
    float* hj;   cudaGetSymbolAddress((void**)&hj,   g_hj);
    float* gbuf; cudaGetSymbolAddress((void**)&gbuf, g_g);
    float* hg;   cudaGetSymbolAddress((void**)&hg,   g_hg);

    const int ROWS = BATCH*NPTS*KNN;   // 16000

    // ---- EdgeConv 1: pos (C=3) -> x1 (32) ----
    run_knn<3>(pos, sqb, d2, knn);
    {
        int all = BATCH*NPTS*KNN*3;
        build_edges_kernel<<<(all + 255)/256, 256>>>(pos, knn, 3, E);
    }
    run_sgemm_small(E, c1_w1, c1_b1, H,   ROWS, 16, 6,  1);
    run_sgemm64   (H, c1_w2, c1_b2, Msg, ROWS, 32, 16, 0);
    {
        int all = BATCH*NPTS*32;
        max_agg_kernel<<<(all + 255)/256, 256>>>(Msg, 32, x1, xcat, 0);
    }

    // ---- EdgeConv 2: x1 (C=32) -> x2 (128) ----
    run_knn<32>(x1, sqb, d2, knn);
    {
        int all = BATCH*NPTS*KNN*32;
        build_edges_kernel<<<(all + 255)/256, 256>>>(x1, knn, 32, E);
    }
    run_sgemm128(E, c2_w1, c2_b1, H,   ROWS, 64,  64, 1);
    run_sgemm128(H, c2_w2, c2_b2, Msg, ROWS, 128, 64, 0);
    {
        int all = BATCH*NPTS*128;
        max_agg_kernel<<<(all + 255)/256, 256>>>(Msg, 128, x2, xcat, 32);
    }

    // ---- EdgeConv 3: x2 (C=128) -> x3 (512) ----
    run_knn<128>(x2, sqb, d2, knn);
    {
        int all = BATCH*NPTS*KNN*128;
        build_edges_kernel<<<(all + 255)/256, 256>>>(x2, knn, 128, E);
    }
    run_sgemm128(E, c3_w1, c3_b1, H,   ROWS, 256, 256, 1);
    run_sgemm128(H, c3_w2, c3_b2, Msg, ROWS, 512, 256, 0);
    {
        int all = BATCH*NPTS*512;
        max_agg_kernel<<<(all + 255)/256, 256>>>(Msg, 512, nullptr, xcat, 160);
    }

    // ---- shared MLP ----
    run_sgemm64(xcat, sm_w1, sm_b1, H,  BATCH*NPTS, 256, 672, 1);
    run_sgemm64(H,    sm_w2, sm_b2, sf, BATCH*NPTS, 128, 256, 0);

    // ---- global pool + edge classifier pieces ----
    gpool_kernel<<<BATCH, 128>>>(sf, gbuf);
    run_sgemm64(sf, ec_w1,           nullptr, hi, BATCH*NPTS, 128, 128, 0);
    run_sgemm64(sf, ec_w1 + 128*128, nullptr, hj, BATCH*NPTS, 128, 128, 0);
    hg_kernel<<<BATCH, 128>>>(gbuf, ec_w1 + 256*128, ec_b1, hg);

    // ---- all-pairs classifier ----
    {
        dim3 grid((NPTS + 31)/32, (NPTS + 31)/32, BATCH);
        pair_kernel<<<grid, 1024>>>(hi, hj, hg, ec_w2, ec_b2, out);
    }
}

// round 4
// speedup vs baseline: 3.5519x; 1.1911x over previous
#include <cuda_runtime.h>
#include <cuda_bf16.h>
#include <math.h>
#include <float.h>

#define BATCH 2
#define NPTS  1000
#define KNN   8
#define NPAIR ((NPTS*(NPTS-1))/2)   // 499500

// ---------------------------------------------------------------------------
// Static scratch
// ---------------------------------------------------------------------------
__device__ int   g_knn [BATCH*NPTS*KNN];
__device__ float g_sq  [BATCH*NPTS];
__device__ float g_d2  [BATCH*NPTS*NPTS];      // 8 MB distance matrix
__device__ float g_A   [BATCH*NPTS*256];       // per-point x @ W1_top
__device__ float g_B   [BATCH*NPTS*256];       // per-point x @ W1_bot
__device__ float g_H   [BATCH*NPTS*KNN*256];   // per-edge hidden
__device__ float g_Msg [BATCH*NPTS*KNN*512];   // per-edge messages
__device__ float g_x1  [BATCH*NPTS*32];
__device__ float g_x2  [BATCH*NPTS*128];
__device__ float g_xcat[BATCH*NPTS*672];
__device__ float g_sf  [BATCH*NPTS*128];
__device__ float g_hi  [BATCH*NPTS*128];
__device__ float g_hj  [BATCH*NPTS*128];
__device__ float g_g   [BATCH*128];
__device__ float g_hg  [BATCH*128];

// ---------------------------------------------------------------------------
// sq[b,n] = sum_c x^2
// ---------------------------------------------------------------------------
template<int C>
__global__ void sq_kernel(const float* __restrict__ x, float* __restrict__ sq)
{
    int t = blockIdx.x * blockDim.x + threadIdx.x;
    if (t >= BATCH*NPTS) return;
    const float* row = x + (size_t)t * C;
    float s = 0.f;
    #pragma unroll
    for (int c = 0; c < C; c++) s = fmaf(row[c], row[c], s);
    sq[t] = s;
}

// ---------------------------------------------------------------------------
// Pairwise distance: d2[b,n,m] = sq[n] + sq[m] - 2*dot(x_n, x_m)
// ---------------------------------------------------------------------------
template<int C>
__global__ void __launch_bounds__(256)
dist_kernel(const float* __restrict__ x, const float* __restrict__ sq,
            float* __restrict__ d2)
{
    const int b  = blockIdx.z;
    const int n0 = blockIdx.y * 64;
    const int m0 = blockIdx.x * 64;
    const float* xb  = x  + (size_t)b * NPTS * C;
    const float* sqb = sq + b * NPTS;

    __shared__ float As[32][68];
    __shared__ float Bs[32][68];

    const int tid = threadIdx.x;
    const int ti = tid >> 4;
    const int tj = tid & 15;

    float acc[4][4];
    #pragma unroll
    for (int i = 0; i < 4; i++)
        #pragma unroll
        for (int j = 0; j < 4; j++) acc[i][j] = 0.f;

    for (int k0 = 0; k0 < C; k0 += 32) {
        #pragma unroll
        for (int v = tid; v < 512; v += 256) {
            int r  = v >> 3;
            int cq = (v & 7) * 4;
            {
                int row = n0 + r;
                float4 a4 = make_float4(0.f, 0.f, 0.f, 0.f);
                if (row < NPTS) {
                    if ((C & 31) == 0) {
                        a4 = *reinterpret_cast<const float4*>(&xb[(size_t)row*C + k0 + cq]);
                    } else {
                        float tmp[4];
                        #pragma unroll
                        for (int t2 = 0; t2 < 4; t2++) {
                            int k = k0 + cq + t2;
                            tmp[t2] = (k < C) ? xb[(size_t)row*C + k] : 0.f;
                        }
                        a4 = make_float4(tmp[0], tmp[1], tmp[2], tmp[3]);
                    }
                }
                As[cq+0][r] = a4.x; As[cq+1][r] = a4.y;
                As[cq+2][r] = a4.z; As[cq+3][r] = a4.w;
            }
            {
                int row = m0 + r;
                float4 b4 = make_float4(0.f, 0.f, 0.f, 0.f);
                if (row < NPTS) {
                    if ((C & 31) == 0) {
                        b4 = *reinterpret_cast<const float4*>(&xb[(size_t)row*C + k0 + cq]);
                    } else {
                        float tmp[4];
                        #pragma unroll
                        for (int t2 = 0; t2 < 4; t2++) {
                            int k = k0 + cq + t2;
                            tmp[t2] = (k < C) ? xb[(size_t)row*C + k] : 0.f;
                        }
                        b4 = make_float4(tmp[0], tmp[1], tmp[2], tmp[3]);
                    }
                }
                Bs[cq+0][r] = b4.x; Bs[cq+1][r] = b4.y;
                Bs[cq+2][r] = b4.z; Bs[cq+3][r] = b4.w;
            }
        }
        __syncthreads();
        #pragma unroll
        for (int kk = 0; kk < 32; kk++) {
            float ra[4], rb[4];
            *reinterpret_cast<float4*>(ra) = *reinterpret_cast<const float4*>(&As[kk][ti*4]);
            *reinterpret_cast<float4*>(rb) = *reinterpret_cast<const float4*>(&Bs[kk][tj*4]);
            #pragma unroll
            for (int i = 0; i < 4; i++)
                #pragma unroll
                for (int j = 0; j < 4; j++)
                    acc[i][j] = fmaf(ra[i], rb[j], acc[i][j]);
        }
        __syncthreads();
    }

    const int ni = n0 + ti*4;
    const int mj = m0 + tj*4;
    float sqi[4], sqj[4];
    #pragma unroll
    for (int i = 0; i < 4; i++) sqi[i] = (ni+i < NPTS) ? sqb[ni+i] : 0.f;
    #pragma unroll
    for (int j = 0; j < 4; j++) sqj[j] = (mj+j < NPTS) ? sqb[mj+j] : 0.f;
    #pragma unroll
    for (int i = 0; i < 4; i++) {
        if (ni+i >= NPTS) continue;
        #pragma unroll
        for (int j = 0; j < 4; j++) {
            if (mj+j >= NPTS) continue;
            d2[((size_t)b*NPTS + ni+i)*NPTS + mj+j] = sqi[i] + sqj[j] - 2.f*acc[i][j];
        }
    }
}

// ---------------------------------------------------------------------------
// Top-8 per row (ties -> lower idx), coalesced scan + sorted merge tree
// ---------------------------------------------------------------------------
__global__ void topk_kernel(const float* __restrict__ d2, int* __restrict__ knn)
{
    const int b = blockIdx.y;
    const int n = blockIdx.x;
    const int tid = threadIdx.x;   // 128
    const float* row = d2 + ((size_t)b*NPTS + n)*NPTS;

    __shared__ float sd[128*8];
    __shared__ int   si[128*8];

    float bd[8]; int bi[8];
    #pragma unroll
    for (int k = 0; k < 8; k++) { bd[k] = FLT_MAX; bi[k] = 0x7FFFFFFF; }

    for (int m = tid; m < NPTS; m += 128) {
        float d = row[m];
        if (d < bd[7] || (d == bd[7] && m < bi[7])) {
            int p = 7;
            #pragma unroll
            for (int it = 0; it < 7; it++) {
                if (p > 0 && (d < bd[p-1] || (d == bd[p-1] && m < bi[p-1]))) {
                    bd[p] = bd[p-1]; bi[p] = bi[p-1]; p--;
                }
            }
            bd[p] = d; bi[p] = m;
        }
    }
    #pragma unroll
    for (int k = 0; k < 8; k++) { sd[tid*8+k] = bd[k]; si[tid*8+k] = bi[k]; }

    for (int s = 64; s >= 1; s >>= 1) {
        __syncthreads();
        if (tid < s) {
            float* Ad = &sd[tid*8];        int* Ai = &si[tid*8];
            float* Bd = &sd[(tid+s)*8];    int* Bi = &si[(tid+s)*8];
            float od[8]; int oi[8];
            int a = 0, c2 = 0;
            #pragma unroll
            for (int o = 0; o < 8; o++) {
                bool ta = (Ad[a] < Bd[c2]) || (Ad[a] == Bd[c2] && Ai[a] < Bi[c2]);
                if (ta) { od[o] = Ad[a]; oi[o] = Ai[a]; a++; }
                else    { od[o] = Bd[c2]; oi[o] = Bi[c2]; c2++; }
            }
            #pragma unroll
            for (int o = 0; o < 8; o++) { Ad[o] = od[o]; Ai[o] = oi[o]; }
        }
    }
    __syncthreads();
    if (tid < 8) knn[((size_t)b*NPTS + n)*8 + tid] = si[tid];
}

// ---------------------------------------------------------------------------
// Edge combine: H[e] = relu(A[i] + B[j] - B[i] + b1), e=(b,n,k), j=knn[e]
// Nh % 4 == 0, float4 path.
// ---------------------------------------------------------------------------
__global__ void edge_combine_kernel(const float* __restrict__ A,
                                    const float* __restrict__ Bv,
                                    const int* __restrict__ knn,
                                    const float* __restrict__ b1,
                                    float* __restrict__ H, int Nh4)
{
    int t = blockIdx.x * blockDim.x + threadIdx.x;
    int all = BATCH*NPTS*KNN*Nh4;
    if (t >= all) return;
    int c4 = t % Nh4;
    int e  = t / Nh4;
    int n  = (e / KNN) % NPTS;
    int b  = e / (KNN*NPTS);
    int j  = knn[e];
    size_t pi = (size_t)b*NPTS + n;
    size_t pj = (size_t)b*NPTS + j;
    float4 a  = reinterpret_cast<const float4*>(A)[pi*Nh4 + c4];
    float4 bi = reinterpret_cast<const float4*>(Bv)[pi*Nh4 + c4];
    float4 bj = reinterpret_cast<const float4*>(Bv)[pj*Nh4 + c4];
    float4 bb = reinterpret_cast<const float4*>(b1)[c4];
    float4 h;
    h.x = fmaxf(a.x + bj.x - bi.x + bb.x, 0.f);
    h.y = fmaxf(a.y + bj.y - bi.y + bb.y, 0.f);
    h.z = fmaxf(a.z + bj.z - bi.z + bb.z, 0.f);
    h.w = fmaxf(a.w + bj.w - bi.w + bb.w, 0.f);
    reinterpret_cast<float4*>(H)[(size_t)e*Nh4 + c4] = h;
}

// ---------------------------------------------------------------------------
// SGEMM 128x128, BK=16, 8x8 micro. K%16==0, N%4==0.
// ---------------------------------------------------------------------------
__global__ void __launch_bounds__(256, 2)
sgemm128_kernel(const float* __restrict__ A, const float* __restrict__ W,
                const float* __restrict__ bias, float* __restrict__ C,
                int M, int N, int K, int relu)
{
    const int BK = 16;
    __shared__ float As[BK][128];
    __shared__ float Bs[BK][128];

    const int tid = threadIdx.x;
    const int tx = tid & 15;
    const int ty = tid >> 4;
    const int row0 = blockIdx.y * 128;
    const int col0 = blockIdx.x * 128;

    float acc[8][8];
    #pragma unroll
    for (int i = 0; i < 8; i++)
        #pragma unroll
        for (int j = 0; j < 8; j++) acc[i][j] = 0.f;

    for (int k0 = 0; k0 < K; k0 += BK) {
        #pragma unroll
        for (int t = 0; t < 2; t++) {
            int v  = tid + t * 256;
            int m  = v >> 2;
            int kq = (v & 3) * 4;
            int gm = row0 + m;
            float4 a4 = make_float4(0.f, 0.f, 0.f, 0.f);
            if (gm < M)
                a4 = *reinterpret_cast<const float4*>(&A[(size_t)gm * K + k0 + kq]);
            As[kq+0][m] = a4.x; As[kq+1][m] = a4.y;
            As[kq+2][m] = a4.z; As[kq+3][m] = a4.w;
        }
        #pragma unroll
        for (int t = 0; t < 2; t++) {
            int v  = tid + t * 256;
            int n4 = (v & 31) * 4;
            int kk = v >> 5;
            int gn = col0 + n4;
            float4 b4 = make_float4(0.f, 0.f, 0.f, 0.f);
            if (gn < N)
                b4 = *reinterpret_cast<const float4*>(&W[(size_t)(k0 + kk) * N + gn]);
            *reinterpret_cast<float4*>(&Bs[kk][n4]) = b4;
        }
        __syncthreads();
        #pragma unroll
        for (int kk = 0; kk < BK; kk++) {
            float ra[8], rb[8];
            *reinterpret_cast<float4*>(&ra[0]) = *reinterpret_cast<const float4*>(&As[kk][ty*8]);
            *reinterpret_cast<float4*>(&ra[4]) = *reinterpret_cast<const float4*>(&As[kk][ty*8+4]);
            *reinterpret_cast<float4*>(&rb[0]) = *reinterpret_cast<const float4*>(&Bs[kk][tx*8]);
            *reinterpret_cast<float4*>(&rb[4]) = *reinterpret_cast<const float4*>(&Bs[kk][tx*8+4]);
            #pragma unroll
            for (int i = 0; i < 8; i++)
                #pragma unroll
                for (int j = 0; j < 8; j++)
                    acc[i][j] = fmaf(ra[i], rb[j], acc[i][j]);
        }
        __syncthreads();
    }

    float bvals[8];
    #pragma unroll
    for (int j = 0; j < 8; j++) {
        int gn = col0 + tx*8 + j;
        bvals[j] = (bias && gn < N) ? bias[gn] : 0.f;
    }
    #pragma unroll
    for (int i = 0; i < 8; i++) {
        int gm = row0 + ty*8 + i;
        if (gm >= M) continue;
        #pragma unroll
        for (int j = 0; j < 8; j++) {
            int gn = col0 + tx*8 + j;
            if (gn >= N) continue;
            float v = acc[i][j] + bvals[j];
            if (relu) v = fmaxf(v, 0.f);
            C[(size_t)gm * N + gn] = v;
        }
    }
}

// ---------------------------------------------------------------------------
// SGEMM 64x64, BK=16, 4x4 micro. K%16==0, N%4==0.
// ---------------------------------------------------------------------------
__global__ void __launch_bounds__(256)
sgemm64_kernel(const float* __restrict__ A, const float* __restrict__ W,
               const float* __restrict__ bias, float* __restrict__ C,
               int M, int N, int K, int relu)
{
    __shared__ float As[16][64];
    __shared__ float Bs[16][64];

    const int tid = threadIdx.x;
    const int tx = tid & 15;
    const int ty = tid >> 4;
    const int row0 = blockIdx.y * 64;
    const int col0 = blockIdx.x * 64;

    float acc[4][4];
    #pragma unroll
    for (int i = 0; i < 4; i++)
        #pragma unroll
        for (int j = 0; j < 4; j++) acc[i][j] = 0.f;

    for (int k0 = 0; k0 < K; k0 += 16) {
        {
            int m  = tid >> 2;
            int kq = (tid & 3) * 4;
            int gm = row0 + m;
            float4 a4 = make_float4(0.f, 0.f, 0.f, 0.f);
            if (gm < M)
                a4 = *reinterpret_cast<const float4*>(&A[(size_t)gm * K + k0 + kq]);
            As[kq+0][m] = a4.x; As[kq+1][m] = a4.y;
            As[kq+2][m] = a4.z; As[kq+3][m] = a4.w;
        }
        {
            int kk = tid >> 4;
            int n4 = (tid & 15) * 4;
            int gn = col0 + n4;
            float4 b4 = make_float4(0.f, 0.f, 0.f, 0.f);
            if (gn < N)
                b4 = *reinterpret_cast<const float4*>(&W[(size_t)(k0 + kk) * N + gn]);
            *reinterpret_cast<float4*>(&Bs[kk][n4]) = b4;
        }
        __syncthreads();
        #pragma unroll
        for (int kk = 0; kk < 16; kk++) {
            float ra[4], rb[4];
            *reinterpret_cast<float4*>(ra) = *reinterpret_cast<const float4*>(&As[kk][ty*4]);
            *reinterpret_cast<float4*>(rb) = *reinterpret_cast<const float4*>(&Bs[kk][tx*4]);
            #pragma unroll
            for (int i = 0; i < 4; i++)
                #pragma unroll
                for (int j = 0; j < 4; j++)
                    acc[i][j] = fmaf(ra[i], rb[j], acc[i][j]);
        }
        __syncthreads();
    }
    #pragma unroll
    for (int i = 0; i < 4; i++) {
        int gm = row0 + ty*4 + i;
        if (gm >= M) continue;
        #pragma unroll
        for (int j = 0; j < 4; j++) {
            int gn = col0 + tx*4 + j;
            if (gn >= N) continue;
            float v = acc[i][j];
            if (bias) v += bias[gn];
            if (relu) v = fmaxf(v, 0.f);
            C[(size_t)gm * N + gn] = v;
        }
    }
}

// ---------------------------------------------------------------------------
// Naive tiled SGEMM (any K — used for the K=3 point GEMMs of stage 1)
// ---------------------------------------------------------------------------
__global__ void sgemm_kernel(const float* __restrict__ A, const float* __restrict__ W,
                             const float* __restrict__ bias, float* __restrict__ C,
                             int M, int N, int K, int relu)
{
    const int BM = 64, BN = 64, BK = 8, TM = 4, TN = 4;
    __shared__ float As[BK][BM];
    __shared__ float Bs[BK][BN];

    int tid = threadIdx.x;
    int tx = tid % 16, ty = tid / 16;
    int row0 = blockIdx.y * BM;
    int col0 = blockIdx.x * BN;

    float acc[TM][TN];
    #pragma unroll
    for (int i = 0; i < TM; i++)
        #pragma unroll
        for (int j = 0; j < TN; j++) acc[i][j] = 0.f;

    for (int k0 = 0; k0 < K; k0 += BK) {
        for (int i = tid; i < BM*BK; i += 256) {
            int m = i / BK, k = i % BK;
            int gm = row0 + m, gk = k0 + k;
            As[k][m] = (gm < M && gk < K) ? A[(size_t)gm*K + gk] : 0.f;
        }
        for (int i = tid; i < BK*BN; i += 256) {
            int k = i / BN, n = i % BN;
            int gk = k0 + k, gn = col0 + n;
            Bs[k][n] = (gk < K && gn < N) ? W[(size_t)gk*N + gn] : 0.f;
        }
        __syncthreads();
        #pragma unroll
        for (int k = 0; k < BK; k++) {
            float ra[TM], rb[TN];
            #pragma unroll
            for (int i = 0; i < TM; i++) ra[i] = As[k][ty*TM + i];
            #pragma unroll
            for (int j = 0; j < TN; j++) rb[j] = Bs[k][tx*TN + j];
            #pragma unroll
            for (int i = 0; i < TM; i++)
                #pragma unroll
                for (int j = 0; j < TN; j++)
                    acc[i][j] = fmaf(ra[i], rb[j], acc[i][j]);
        }
        __syncthreads();
    }
    #pragma unroll
    for (int i = 0; i < TM; i++) {
        int gm = row0 + ty*TM + i;
        if (gm >= M) continue;
        #pragma unroll
        for (int j = 0; j < TN; j++) {
            int gn = col0 + tx*TN + j;
            if (gn >= N) continue;
            float v = acc[i][j];
            if (bias) v += bias[gn];
            if (relu) v = fmaxf(v, 0.f);
            C[(size_t)gm*N + gn] = v;
        }
    }
}

// ---------------------------------------------------------------------------
// Max-aggregate over 8 neighbors (float4)
// ---------------------------------------------------------------------------
__global__ void max_agg4_kernel(const float* __restrict__ Msg, int Cout4,
                                float* __restrict__ xout,
                                float* __restrict__ xcat, int cat_off)
{
    int t = blockIdx.x * blockDim.x + threadIdx.x;
    int total = BATCH*NPTS*Cout4;
    if (t >= total) return;
    int c4 = t % Cout4;
    int p  = t / Cout4;
    float4 v = make_float4(-FLT_MAX, -FLT_MAX, -FLT_MAX, -FLT_MAX);
    #pragma unroll
    for (int k = 0; k < KNN; k++) {
        float4 m = reinterpret_cast<const float4*>(Msg)[((size_t)p*KNN + k)*Cout4 + c4];
        v.x = fmaxf(v.x, m.x); v.y = fmaxf(v.y, m.y);
        v.z = fmaxf(v.z, m.z); v.w = fmaxf(v.w, m.w);
    }
    if (xout) reinterpret_cast<float4*>(xout)[(size_t)p*Cout4 + c4] = v;
    reinterpret_cast<float4*>(&xcat[(size_t)p*672 + cat_off])[c4] = v;
}

// ---------------------------------------------------------------------------
// Global max pool over N, 1024 threads per batch
// ---------------------------------------------------------------------------
__global__ void gpool_kernel(const float* __restrict__ sf, float* __restrict__ g)
{
    __shared__ float red[1024];
    int b = blockIdx.x;
    int c = threadIdx.x & 127;
    int slice = threadIdx.x >> 7;   // 0..7
    float v = -FLT_MAX;
    for (int n = slice; n < NPTS; n += 8)
        v = fmaxf(v, sf[(((size_t)b*NPTS) + n)*128 + c]);
    red[threadIdx.x] = v;
    __syncthreads();
    if (threadIdx.x < 512) red[threadIdx.x] = fmaxf(red[threadIdx.x], red[threadIdx.x+512]);
    __syncthreads();
    if (threadIdx.x < 256) red[threadIdx.x] = fmaxf(red[threadIdx.x], red[threadIdx.x+256]);
    __syncthreads();
    if (threadIdx.x < 128) g[b*128 + c] = fmaxf(red[threadIdx.x], red[threadIdx.x+128]);
}

// ---------------------------------------------------------------------------
// hg[b,c] = g[b] @ ec_w1[256:384] + ec_b1
// ---------------------------------------------------------------------------
__global__ void hg_kernel(const float* __restrict__ g, const float* __restrict__ w,
                          const float* __restrict__ b1, float* __restrict__ hg)
{
    int b = blockIdx.x, c = threadIdx.x;
    float acc = b1[c];
    for (int k = 0; k < 128; k++)
        acc = fmaf(g[b*128 + k], w[k*128 + c], acc);
    hg[b*128 + c] = acc;
}

// ---------------------------------------------------------------------------
// Pair kernel: 64x64 pair tiles, 256 threads, 4x4 micro, c in 2 chunks of 64.
// hi already includes hg (folded as GEMM bias). hidden = relu(hi'[i]+hj[j]).
// ---------------------------------------------------------------------------
__global__ void __launch_bounds__(256)
pair_kernel(const float* __restrict__ hi, const float* __restrict__ hj,
            const float* __restrict__ w2, const float* __restrict__ b2p,
            float* __restrict__ out)
{
    const int b  = blockIdx.z;
    const int i0 = blockIdx.y * 64;
    const int j0 = blockIdx.x * 64;
    if (j0 + 63 <= i0) return;   // whole tile has j <= i

    __shared__ float shi[64][65];
    __shared__ float shj[64][65];
    __shared__ float sw2[128];

    const int tid = threadIdx.x;
    const int ti = tid >> 4;   // 0..15 -> rows ti*4+q
    const int tj = tid & 15;   // 0..15 -> cols tj+16*s

    if (tid < 128) sw2[tid] = w2[tid];

    float acc[4][4];
    #pragma unroll
    for (int q = 0; q < 4; q++)
        #pragma unroll
        for (int s = 0; s < 4; s++) acc[q][s] = 0.f;

    for (int c0 = 0; c0 < 128; c0 += 64) {
        __syncthreads();
        #pragma unroll
        for (int it = 0; it < 16; it++) {
            int idx = tid + it * 256;
            int r = idx >> 6, c = idx & 63;
            int gi = i0 + r, gj = j0 + r;
            shi[r][c] = (gi < NPTS) ? hi[(((size_t)b*NPTS) + gi)*128 + c0 + c] : 0.f;
            shj[r][c] = (gj < NPTS) ? hj[(((size_t)b*NPTS) + gj)*128 + c0 + c] : 0.f;
        }
        __syncthreads();
        #pragma unroll 8
        for (int c = 0; c < 64; c++) {
            float w = sw2[c0 + c];
            float ri[4], rj[4];
            #pragma unroll
            for (int q = 0; q < 4; q++) ri[q] = shi[ti*4 + q][c];
            #pragma unroll
            for (int s = 0; s < 4; s++) rj[s] = shj[tj + 16*s][c];
            #pragma unroll
            for (int q = 0; q < 4; q++)
                #pragma unroll
                for (int s = 0; s < 4; s++)
                    acc[q][s] = fmaf(fmaxf(ri[q] + rj[s], 0.f), w, acc[q][s]);
        }
    }

    const float bb = b2p[0];
    #pragma unroll
    for (int q = 0; q < 4; q++) {
        int i = i0 + ti*4 + q;
        if (i >= NPTS) continue;
        #pragma unroll
        for (int s = 0; s < 4; s++) {
            int j = j0 + tj + 16*s;
            if (j < NPTS && i < j) {
                float lg = acc[q][s] + bb;
                int p = i*NPTS - (i*(i+1))/2 + (j - i - 1);
                out[(size_t)b*NPAIR + p] = 1.f / (1.f + expf(-lg));
                out[(size_t)BATCH*NPAIR + (size_t)b*NPAIR + p] = lg;
            }
        }
    }
}

// ---------------------------------------------------------------------------
// Launch helpers
// ---------------------------------------------------------------------------
static inline void run_sgemm_small(const float* A, const float* W, const float* bias,
                                   float* C, int M, int N, int K, int relu)
{
    dim3 grid((N + 63)/64, (M + 63)/64);
    sgemm_kernel<<<grid, 256>>>(A, W, bias, C, M, N, K, relu);
}
static inline void run_sgemm128(const float* A, const float* W, const float* bias,
                                float* C, int M, int N, int K, int relu)
{
    dim3 grid((N + 127)/128, (M + 127)/128);
    sgemm128_kernel<<<grid, 256>>>(A, W, bias, C, M, N, K, relu);
}
static inline void run_sgemm64(const float* A, const float* W, const float* bias,
                               float* C, int M, int N, int K, int relu)
{
    dim3 grid((N + 63)/64, (M + 63)/64);
    sgemm64_kernel<<<grid, 256>>>(A, W, bias, C, M, N, K, relu);
}

template<int C>
static inline void run_knn(const float* x, float* sqb, float* d2, int* knn)
{
    sq_kernel<C><<<(BATCH*NPTS + 127)/128, 128>>>(x, sqb);
    dim3 dgrid((NPTS + 63)/64, (NPTS + 63)/64, BATCH);
    dist_kernel<C><<<dgrid, 256>>>(x, sqb, d2);
    dim3 tgrid(NPTS, BATCH);
    topk_kernel<<<tgrid, 128>>>(d2, knn);
}

extern "C" void kernel_launch(void* const* d_in, const int* in_sizes, int n_in,
                              void* d_out, int out_size)
{
    const float* pos   = (const float*)d_in[0];
    const float* c1_w1 = (const float*)d_in[1];
    const float* c1_b1 = (const float*)d_in[2];
    const float* c1_w2 = (const float*)d_in[3];
    const float* c1_b2 = (const float*)d_in[4];
    const float* c2_w1 = (const float*)d_in[5];
    const float* c2_b1 = (const float*)d_in[6];
    const float* c2_w2 = (const float*)d_in[7];
    const float* c2_b2 = (const float*)d_in[8];
    const float* c3_w1 = (const float*)d_in[9];
    const float* c3_b1 = (const float*)d_in[10];
    const float* c3_w2 = (const float*)d_in[11];
    const float* c3_b2 = (const float*)d_in[12];
    const float* sm_w1 = (const float*)d_in[13];
    const float* sm_b1 = (const float*)d_in[14];
    const float* sm_w2 = (const float*)d_in[15];
    const float* sm_b2 = (const float*)d_in[16];
    const float* ec_w1 = (const float*)d_in[17];
    const float* ec_b1 = (const float*)d_in[18];
    const float* ec_w2 = (const float*)d_in[19];
    const float* ec_b2 = (const float*)d_in[20];

    float* out = (float*)d_out;

    int*   knn;  cudaGetSymbolAddress((void**)&knn,  g_knn);
    float* sqb;  cudaGetSymbolAddress((void**)&sqb,  g_sq);
    float* d2;   cudaGetSymbolAddress((void**)&d2,   g_d2);
    float* Ab;   cudaGetSymbolAddress((void**)&Ab,   g_A);
    float* Bb;   cudaGetSymbolAddress((void**)&Bb,   g_B);
    float* H;    cudaGetSymbolAddress((void**)&H,    g_H);
    float* Msg;  cudaGetSymbolAddress((void**)&Msg,  g_Msg);
    float* x1;   cudaGetSymbolAddress((void**)&x1,   g_x1);
    float* x2;   cudaGetSymbolAddress((void**)&x2,   g_x2);
    float* xcat; cudaGetSymbolAddress((void**)&xcat, g_xcat);
    float* sf;   cudaGetSymbolAddress((void**)&sf,   g_sf);
    float* hi;   cudaGetSymbolAddress((void**)&hi,   g_hi);
    float* hj;   cudaGetSymbolAddress((void**)&hj,   g_hj);
    float* gbuf; cudaGetSymbolAddress((void**)&gbuf, g_g);
    float* hg;   cudaGetSymbolAddress((void**)&hg,   g_hg);

    const int ROWS = BATCH*NPTS*KNN;   // 16000
    const int PTS  = BATCH*NPTS;       // 2000

    // ======== EdgeConv 1: pos (C=3) -> x1 (32) ========
    run_knn<3>(pos, sqb, d2, knn);
    // A = pos @ W1[0:3], B = pos @ W1[3:6]   (W1: (6,16) row-major)
    run_sgemm_small(pos, c1_w1,          nullptr, Ab, PTS, 16, 3, 0);
    run_sgemm_small(pos, c1_w1 + 3*16,   nullptr, Bb, PTS, 16, 3, 0);
    edge_combine_kernel<<<(ROWS*4 + 255)/256, 256>>>(Ab, Bb, knn, c1_b1, H, 4);     // Nh=16
    run_sgemm64(H, c1_w2, c1_b2, Msg, ROWS, 32, 16, 0);
    max_agg4_kernel<<<(PTS*8 + 255)/256, 256>>>(Msg, 8, x1, xcat, 0);               // Cout=32

    // ======== EdgeConv 2: x1 (C=32) -> x2 (128) ========
    run_knn<32>(x1, sqb, d2, knn);
    run_sgemm64(x1, c2_w1,           nullptr, Ab, PTS, 64, 32, 0);
    run_sgemm64(x1, c2_w1 + 32*64,   nullptr, Bb, PTS, 64, 32, 0);
    edge_combine_kernel<<<(ROWS*16 + 255)/256, 256>>>(Ab, Bb, knn, c2_b1, H, 16);   // Nh=64
    run_sgemm128(H, c2_w2, c2_b2, Msg, ROWS, 128, 64, 0);
    max_agg4_kernel<<<(PTS*32 + 255)/256, 256>>>(Msg, 32, x2, xcat, 32);            // Cout=128

    // ======== EdgeConv 3: x2 (C=128) -> x3 (512) ========
    run_knn<128>(x2, sqb, d2, knn);
    run_sgemm64(x2, c3_w1,             nullptr, Ab, PTS, 256, 128, 0);
    run_sgemm64(x2, c3_w1 + 128*256,   nullptr, Bb, PTS, 256, 128, 0);
    edge_combine_kernel<<<(ROWS*64 + 255)/256, 256>>>(Ab, Bb, knn, c3_b1, H, 64);   // Nh=256
    run_sgemm128(H, c3_w2, c3_b2, Msg, ROWS, 512, 256, 0);
    max_agg4_kernel<<<(PTS*128 + 255)/256, 256>>>(Msg, 128, nullptr, xcat, 160);    // Cout=512

    // ======== shared MLP: xcat[2000,672] -> 256 (relu) -> sf[2000,128] ========
    run_sgemm64(xcat, sm_w1, sm_b1, H,  PTS, 256, 672, 1);
    run_sgemm64(H,    sm_w2, sm_b2, sf, PTS, 128, 256, 0);

    // ======== global pool + edge classifier pieces ========
    gpool_kernel<<<BATCH, 1024>>>(sf, gbuf);
    hg_kernel<<<BATCH, 128>>>(gbuf, ec_w1 + 256*128, ec_b1, hg);
    // hi' = sf @ W_hi + hg  (per batch, hg as column bias); hj = sf @ W_hj
    run_sgemm64(sf,               ec_w1, hg,        hi,               1000, 128, 128, 0);
    run_sgemm64(sf + 1000*128,    ec_w1, hg + 128,  hi + 1000*128,    1000, 128, 128, 0);
    run_sgemm64(sf, ec_w1 + 128*128, nullptr, hj, PTS, 128, 128, 0);

    // ======== all-pairs classifier ========
    {
        dim3 grid((NPTS + 63)/64, (NPTS + 63)/64, BATCH);
        pair_kernel<<<grid, 256>>>(hi, hj, ec_w2, ec_b2, out);
    }
}

// round 5
// speedup vs baseline: 3.7924x; 1.0677x over previous
#include <cuda_runtime.h>
#include <cuda_bf16.h>
#include <math.h>
#include <float.h>

#define BATCH 2
#define NPTS  1000
#define KNN   8
#define NPAIR ((NPTS*(NPTS-1))/2)   // 499500

// ---------------------------------------------------------------------------
// Static scratch
// ---------------------------------------------------------------------------
__device__ int   g_knn [BATCH*NPTS*KNN];
__device__ float g_sq  [BATCH*NPTS];
__device__ float g_d2  [BATCH*NPTS*NPTS];      // 8 MB distance matrix
__device__ float g_A   [BATCH*NPTS*256];       // per-point x @ W1_top
__device__ float g_B   [BATCH*NPTS*256];       // per-point x @ W1_bot
__device__ float g_H   [BATCH*NPTS*KNN*256];   // per-edge hidden / sm hidden
__device__ float g_Msg [BATCH*NPTS*KNN*512];   // per-edge messages
__device__ float g_T   [16000*256];            // transposed activations (16.4 MB)
__device__ float g_x1  [BATCH*NPTS*32];
__device__ float g_x2  [BATCH*NPTS*128];
__device__ float g_xcat[BATCH*NPTS*672];
__device__ float g_sf  [BATCH*NPTS*128];
__device__ float g_hi  [BATCH*NPTS*128];
__device__ float g_hj  [BATCH*NPTS*128];
__device__ float g_g   [BATCH*128];
__device__ float g_hg  [BATCH*128];

// ---------------------------------------------------------------------------
// cp.async helpers
// ---------------------------------------------------------------------------
__device__ __forceinline__ void cp_async16(void* smem_ptr, const void* gmem_ptr) {
    unsigned dst = (unsigned)__cvta_generic_to_shared(smem_ptr);
    asm volatile("cp.async.cg.shared.global [%0], [%1], 16;\n" :: "r"(dst), "l"(gmem_ptr));
}
__device__ __forceinline__ void cp_commit() { asm volatile("cp.async.commit_group;\n" ::: "memory"); }
__device__ __forceinline__ void cp_wait0()  { asm volatile("cp.async.wait_group 0;\n" ::: "memory"); }

// ---------------------------------------------------------------------------
// sq[b,n] = sum_c x^2
// ---------------------------------------------------------------------------
template<int C>
__global__ void sq_kernel(const float* __restrict__ x, float* __restrict__ sq)
{
    int t = blockIdx.x * blockDim.x + threadIdx.x;
    if (t >= BATCH*NPTS) return;
    const float* row = x + (size_t)t * C;
    float s = 0.f;
    #pragma unroll
    for (int c = 0; c < C; c++) s = fmaf(row[c], row[c], s);
    sq[t] = s;
}

// ---------------------------------------------------------------------------
// Pairwise distance: d2[b,n,m] = sq[n] + sq[m] - 2*dot(x_n, x_m)
// ---------------------------------------------------------------------------
template<int C>
__global__ void __launch_bounds__(256)
dist_kernel(const float* __restrict__ x, const float* __restrict__ sq,
            float* __restrict__ d2)
{
    const int b  = blockIdx.z;
    const int n0 = blockIdx.y * 64;
    const int m0 = blockIdx.x * 64;
    const float* xb  = x  + (size_t)b * NPTS * C;
    const float* sqb = sq + b * NPTS;

    __shared__ float As[32][68];
    __shared__ float Bs[32][68];

    const int tid = threadIdx.x;
    const int ti = tid >> 4;
    const int tj = tid & 15;

    float acc[4][4];
    #pragma unroll
    for (int i = 0; i < 4; i++)
        #pragma unroll
        for (int j = 0; j < 4; j++) acc[i][j] = 0.f;

    for (int k0 = 0; k0 < C; k0 += 32) {
        #pragma unroll
        for (int v = tid; v < 512; v += 256) {
            int r  = v >> 3;
            int cq = (v & 7) * 4;
            {
                int row = n0 + r;
                float4 a4 = make_float4(0.f, 0.f, 0.f, 0.f);
                if (row < NPTS) {
                    if ((C & 31) == 0) {
                        a4 = *reinterpret_cast<const float4*>(&xb[(size_t)row*C + k0 + cq]);
                    } else {
                        float tmp[4];
                        #pragma unroll
                        for (int t2 = 0; t2 < 4; t2++) {
                            int k = k0 + cq + t2;
                            tmp[t2] = (k < C) ? xb[(size_t)row*C + k] : 0.f;
                        }
                        a4 = make_float4(tmp[0], tmp[1], tmp[2], tmp[3]);
                    }
                }
                As[cq+0][r] = a4.x; As[cq+1][r] = a4.y;
                As[cq+2][r] = a4.z; As[cq+3][r] = a4.w;
            }
            {
                int row = m0 + r;
                float4 b4 = make_float4(0.f, 0.f, 0.f, 0.f);
                if (row < NPTS) {
                    if ((C & 31) == 0) {
                        b4 = *reinterpret_cast<const float4*>(&xb[(size_t)row*C + k0 + cq]);
                    } else {
                        float tmp[4];
                        #pragma unroll
                        for (int t2 = 0; t2 < 4; t2++) {
                            int k = k0 + cq + t2;
                            tmp[t2] = (k < C) ? xb[(size_t)row*C + k] : 0.f;
                        }
                        b4 = make_float4(tmp[0], tmp[1], tmp[2], tmp[3]);
                    }
                }
                Bs[cq+0][r] = b4.x; Bs[cq+1][r] = b4.y;
                Bs[cq+2][r] = b4.z; Bs[cq+3][r] = b4.w;
            }
        }
        __syncthreads();
        #pragma unroll
        for (int kk = 0; kk < 32; kk++) {
            float ra[4], rb[4];
            *reinterpret_cast<float4*>(ra) = *reinterpret_cast<const float4*>(&As[kk][ti*4]);
            *reinterpret_cast<float4*>(rb) = *reinterpret_cast<const float4*>(&Bs[kk][tj*4]);
            #pragma unroll
            for (int i = 0; i < 4; i++)
                #pragma unroll
                for (int j = 0; j < 4; j++)
                    acc[i][j] = fmaf(ra[i], rb[j], acc[i][j]);
        }
        __syncthreads();
    }

    const int ni = n0 + ti*4;
    const int mj = m0 + tj*4;
    float sqi[4], sqj[4];
    #pragma unroll
    for (int i = 0; i < 4; i++) sqi[i] = (ni+i < NPTS) ? sqb[ni+i] : 0.f;
    #pragma unroll
    for (int j = 0; j < 4; j++) sqj[j] = (mj+j < NPTS) ? sqb[mj+j] : 0.f;
    #pragma unroll
    for (int i = 0; i < 4; i++) {
        if (ni+i >= NPTS) continue;
        #pragma unroll
        for (int j = 0; j < 4; j++) {
            if (mj+j >= NPTS) continue;
            d2[((size_t)b*NPTS + ni+i)*NPTS + mj+j] = sqi[i] + sqj[j] - 2.f*acc[i][j];
        }
    }
}

// ---------------------------------------------------------------------------
// Top-8 per row (ties -> lower idx)
// ---------------------------------------------------------------------------
__global__ void topk_kernel(const float* __restrict__ d2, int* __restrict__ knn)
{
    const int b = blockIdx.y;
    const int n = blockIdx.x;
    const int tid = threadIdx.x;   // 128
    const float* row = d2 + ((size_t)b*NPTS + n)*NPTS;

    __shared__ float sd[128*8];
    __shared__ int   si[128*8];

    float bd[8]; int bi[8];
    #pragma unroll
    for (int k = 0; k < 8; k++) { bd[k] = FLT_MAX; bi[k] = 0x7FFFFFFF; }

    for (int m = tid; m < NPTS; m += 128) {
        float d = row[m];
        if (d < bd[7] || (d == bd[7] && m < bi[7])) {
            int p = 7;
            #pragma unroll
            for (int it = 0; it < 7; it++) {
                if (p > 0 && (d < bd[p-1] || (d == bd[p-1] && m < bi[p-1]))) {
                    bd[p] = bd[p-1]; bi[p] = bi[p-1]; p--;
                }
            }
            bd[p] = d; bi[p] = m;
        }
    }
    #pragma unroll
    for (int k = 0; k < 8; k++) { sd[tid*8+k] = bd[k]; si[tid*8+k] = bi[k]; }

    for (int s = 64; s >= 1; s >>= 1) {
        __syncthreads();
        if (tid < s) {
            float* Ad = &sd[tid*8];        int* Ai = &si[tid*8];
            float* Bd = &sd[(tid+s)*8];    int* Bi = &si[(tid+s)*8];
            float od[8]; int oi[8];
            int a = 0, c2 = 0;
            #pragma unroll
            for (int o = 0; o < 8; o++) {
                bool ta = (Ad[a] < Bd[c2]) || (Ad[a] == Bd[c2] && Ai[a] < Bi[c2]);
                if (ta) { od[o] = Ad[a]; oi[o] = Ai[a]; a++; }
                else    { od[o] = Bd[c2]; oi[o] = Bi[c2]; c2++; }
            }
            #pragma unroll
            for (int o = 0; o < 8; o++) { Ad[o] = od[o]; Ai[o] = oi[o]; }
        }
    }
    __syncthreads();
    if (tid < 8) knn[((size_t)b*NPTS + n)*8 + tid] = si[tid];
}

// ---------------------------------------------------------------------------
// Transpose: out[k][m] = in[m][k]   (in: M x K), 32x32 smem tiles
// ---------------------------------------------------------------------------
__global__ void transpose_kernel(const float* __restrict__ in, float* __restrict__ outp,
                                 int M, int K)
{
    __shared__ float tile[32][33];
    const int k0 = blockIdx.x * 32;
    const int m0 = blockIdx.y * 32;
    const int tx = threadIdx.x & 31;
    const int ty = threadIdx.x >> 5;   // 0..7
    #pragma unroll
    for (int r = ty; r < 32; r += 8) {
        int m = m0 + r, k = k0 + tx;
        tile[r][tx] = (m < M && k < K) ? in[(size_t)m*K + k] : 0.f;
    }
    __syncthreads();
    #pragma unroll
    for (int r = ty; r < 32; r += 8) {
        int k = k0 + r, m = m0 + tx;
        if (k < K && m < M) outp[(size_t)k*M + m] = tile[tx][r];
    }
}

// ---------------------------------------------------------------------------
// Double-buffered cp.async SGEMM: C[M,N] = act(A @ W + bias)
// A supplied TRANSPOSED: AT[k][m] with row stride lda. W: [K][N].
// Requires K % BK == 0, N % BN == 0, (GUARDM ? M%4==0 : M%BM==0).
// ---------------------------------------------------------------------------
template<int BM, int BN, int BK, int TM, int TN, bool GUARDM>
__global__ void __launch_bounds__(256, 2)
sgemm_db_kernel(const float* __restrict__ AT, int lda,
                const float* __restrict__ W,
                const float* __restrict__ bias, float* __restrict__ C,
                int M, int N, int K, int relu)
{
    __shared__ float As[2][BK][BM];
    __shared__ float Bs[2][BK][BN];

    const int tid = threadIdx.x;
    constexpr int NTX = BN / TN;
    const int tx = tid % NTX;
    const int ty = tid / NTX;
    const int row0 = blockIdx.y * BM;
    const int col0 = blockIdx.x * BN;

    float acc[TM][TN];
    #pragma unroll
    for (int i = 0; i < TM; i++)
        #pragma unroll
        for (int j = 0; j < TN; j++) acc[i][j] = 0.f;

    auto load_tile = [&](int buf, int k0) {
        constexpr int CHA = BM*BK/4;
        #pragma unroll
        for (int t = 0; t < CHA/256; t++) {
            int c  = tid + t*256;
            int kk = c / (BM/4);
            int m4 = (c % (BM/4)) * 4;
            int gm = row0 + m4;
            if (GUARDM) gm = min(gm, M - 4);
            cp_async16(&As[buf][kk][m4], &AT[(size_t)(k0+kk)*lda + gm]);
        }
        constexpr int CHB = BN*BK/4;
        #pragma unroll
        for (int t = 0; t < CHB/256; t++) {
            int c  = tid + t*256;
            int kk = c / (BN/4);
            int n4 = (c % (BN/4)) * 4;
            cp_async16(&Bs[buf][kk][n4], &W[(size_t)(k0+kk)*N + col0 + n4]);
        }
    };

    load_tile(0, 0);
    cp_commit();
    int buf = 0;
    for (int k0 = 0; k0 < K; k0 += BK) {
        cp_wait0();
        __syncthreads();
        if (k0 + BK < K) { load_tile(buf ^ 1, k0 + BK); cp_commit(); }
        #pragma unroll
        for (int kk = 0; kk < BK; kk++) {
            float ra[TM], rb[TN];
            #pragma unroll
            for (int i = 0; i < TM; i += 4)
                *reinterpret_cast<float4*>(&ra[i]) =
                    *reinterpret_cast<const float4*>(&As[buf][kk][ty*TM + i]);
            #pragma unroll
            for (int j = 0; j < TN; j += 4)
                *reinterpret_cast<float4*>(&rb[j]) =
                    *reinterpret_cast<const float4*>(&Bs[buf][kk][tx*TN + j]);
            #pragma unroll
            for (int i = 0; i < TM; i++)
                #pragma unroll
                for (int j = 0; j < TN; j++)
                    acc[i][j] = fmaf(ra[i], rb[j], acc[i][j]);
        }
        buf ^= 1;
    }

    float bvals[TN];
    #pragma unroll
    for (int j = 0; j < TN; j++)
        bvals[j] = bias ? bias[col0 + tx*TN + j] : 0.f;

    #pragma unroll
    for (int i = 0; i < TM; i++) {
        int gm = row0 + ty*TM + i;
        if (GUARDM && gm >= M) continue;
        #pragma unroll
        for (int j = 0; j < TN; j++) {
            float v = acc[i][j] + bvals[j];
            if (relu) v = fmaxf(v, 0.f);
            C[(size_t)gm * N + col0 + tx*TN + j] = v;
        }
    }
}

// ---------------------------------------------------------------------------
// Classic SGEMM 64x64, BK=16, 4x4 micro (A row-major). K%16==0, N%4==0.
// ---------------------------------------------------------------------------
__global__ void __launch_bounds__(256)
sgemm64_kernel(const float* __restrict__ A, const float* __restrict__ W,
               const float* __restrict__ bias, float* __restrict__ C,
               int M, int N, int K, int relu)
{
    __shared__ float As[16][64];
    __shared__ float Bs[16][64];

    const int tid = threadIdx.x;
    const int tx = tid & 15;
    const int ty = tid >> 4;
    const int row0 = blockIdx.y * 64;
    const int col0 = blockIdx.x * 64;

    float acc[4][4];
    #pragma unroll
    for (int i = 0; i < 4; i++)
        #pragma unroll
        for (int j = 0; j < 4; j++) acc[i][j] = 0.f;

    for (int k0 = 0; k0 < K; k0 += 16) {
        {
            int m  = tid >> 2;
            int kq = (tid & 3) * 4;
            int gm = row0 + m;
            float4 a4 = make_float4(0.f, 0.f, 0.f, 0.f);
            if (gm < M)
                a4 = *reinterpret_cast<const float4*>(&A[(size_t)gm * K + k0 + kq]);
            As[kq+0][m] = a4.x; As[kq+1][m] = a4.y;
            As[kq+2][m] = a4.z; As[kq+3][m] = a4.w;
        }
        {
            int kk = tid >> 4;
            int n4 = (tid & 15) * 4;
            int gn = col0 + n4;
            float4 b4 = make_float4(0.f, 0.f, 0.f, 0.f);
            if (gn < N)
                b4 = *reinterpret_cast<const float4*>(&W[(size_t)(k0 + kk) * N + gn]);
            *reinterpret_cast<float4*>(&Bs[kk][n4]) = b4;
        }
        __syncthreads();
        #pragma unroll
        for (int kk = 0; kk < 16; kk++) {
            float ra[4], rb[4];
            *reinterpret_cast<float4*>(ra) = *reinterpret_cast<const float4*>(&As[kk][ty*4]);
            *reinterpret_cast<float4*>(rb) = *reinterpret_cast<const float4*>(&Bs[kk][tx*4]);
            #pragma unroll
            for (int i = 0; i < 4; i++)
                #pragma unroll
                for (int j = 0; j < 4; j++)
                    acc[i][j] = fmaf(ra[i], rb[j], acc[i][j]);
        }
        __syncthreads();
    }
    #pragma unroll
    for (int i = 0; i < 4; i++) {
        int gm = row0 + ty*4 + i;
        if (gm >= M) continue;
        #pragma unroll
        for (int j = 0; j < 4; j++) {
            int gn = col0 + tx*4 + j;
            if (gn >= N) continue;
            float v = acc[i][j];
            if (bias) v += bias[gn];
            if (relu) v = fmaxf(v, 0.f);
            C[(size_t)gm * N + gn] = v;
        }
    }
}

// ---------------------------------------------------------------------------
// Stage-1 fused layer 1: H[e][nh] = relu([xi, xj-xi] @ W1 + b1), C=3, Nh=16
// ---------------------------------------------------------------------------
__global__ void edge1_kernel(const float* __restrict__ pos, const int* __restrict__ knn,
                             const float* __restrict__ W1, const float* __restrict__ b1,
                             float* __restrict__ H)
{
    int t = blockIdx.x * blockDim.x + threadIdx.x;
    if (t >= BATCH*NPTS*KNN*16) return;
    int nh = t & 15;
    int e  = t >> 4;
    int n  = (e / KNN) % NPTS;
    int b  = e / (KNN*NPTS);
    int j  = knn[e];
    const float* xi = pos + (((size_t)b*NPTS) + n)*3;
    const float* xj = pos + (((size_t)b*NPTS) + j)*3;
    float acc = b1[nh];
    #pragma unroll
    for (int c = 0; c < 3; c++) {
        acc = fmaf(xi[c],          W1[c*16 + nh],     acc);
        acc = fmaf(xj[c] - xi[c],  W1[(3+c)*16 + nh], acc);
    }
    H[(size_t)e*16 + nh] = fmaxf(acc, 0.f);
}

// ---------------------------------------------------------------------------
// Edge combine: H[e] = relu(A[i] + B[j] - B[i] + b1)
// ---------------------------------------------------------------------------
__global__ void edge_combine_kernel(const float* __restrict__ A,
                                    const float* __restrict__ Bv,
                                    const int* __restrict__ knn,
                                    const float* __restrict__ b1,
                                    float* __restrict__ H, int Nh4)
{
    int t = blockIdx.x * blockDim.x + threadIdx.x;
    int all = BATCH*NPTS*KNN*Nh4;
    if (t >= all) return;
    int c4 = t % Nh4;
    int e  = t / Nh4;
    int n  = (e / KNN) % NPTS;
    int b  = e / (KNN*NPTS);
    int j  = knn[e];
    size_t pi = (size_t)b*NPTS + n;
    size_t pj = (size_t)b*NPTS + j;
    float4 a  = reinterpret_cast<const float4*>(A)[pi*Nh4 + c4];
    float4 bi = reinterpret_cast<const float4*>(Bv)[pi*Nh4 + c4];
    float4 bj = reinterpret_cast<const float4*>(Bv)[pj*Nh4 + c4];
    float4 bb = reinterpret_cast<const float4*>(b1)[c4];
    float4 h;
    h.x = fmaxf(a.x + bj.x - bi.x + bb.x, 0.f);
    h.y = fmaxf(a.y + bj.y - bi.y + bb.y, 0.f);
    h.z = fmaxf(a.z + bj.z - bi.z + bb.z, 0.f);
    h.w = fmaxf(a.w + bj.w - bi.w + bb.w, 0.f);
    reinterpret_cast<float4*>(H)[(size_t)e*Nh4 + c4] = h;
}

// ---------------------------------------------------------------------------
// Max-aggregate over 8 neighbors (float4)
// ---------------------------------------------------------------------------
__global__ void max_agg4_kernel(const float* __restrict__ Msg, int Cout4,
                                float* __restrict__ xout,
                                float* __restrict__ xcat, int cat_off)
{
    int t = blockIdx.x * blockDim.x + threadIdx.x;
    int total = BATCH*NPTS*Cout4;
    if (t >= total) return;
    int c4 = t % Cout4;
    int p  = t / Cout4;
    float4 v = make_float4(-FLT_MAX, -FLT_MAX, -FLT_MAX, -FLT_MAX);
    #pragma unroll
    for (int k = 0; k < KNN; k++) {
        float4 m = reinterpret_cast<const float4*>(Msg)[((size_t)p*KNN + k)*Cout4 + c4];
        v.x = fmaxf(v.x, m.x); v.y = fmaxf(v.y, m.y);
        v.z = fmaxf(v.z, m.z); v.w = fmaxf(v.w, m.w);
    }
    if (xout) reinterpret_cast<float4*>(xout)[(size_t)p*Cout4 + c4] = v;
    reinterpret_cast<float4*>(&xcat[(size_t)p*672 + cat_off])[c4] = v;
}

// ---------------------------------------------------------------------------
// Global max pool over N
// ---------------------------------------------------------------------------
__global__ void gpool_kernel(const float* __restrict__ sf, float* __restrict__ g)
{
    __shared__ float red[1024];
    int b = blockIdx.x;
    int c = threadIdx.x & 127;
    int slice = threadIdx.x >> 7;
    float v = -FLT_MAX;
    for (int n = slice; n < NPTS; n += 8)
        v = fmaxf(v, sf[(((size_t)b*NPTS) + n)*128 + c]);
    red[threadIdx.x] = v;
    __syncthreads();
    if (threadIdx.x < 512) red[threadIdx.x] = fmaxf(red[threadIdx.x], red[threadIdx.x+512]);
    __syncthreads();
    if (threadIdx.x < 256) red[threadIdx.x] = fmaxf(red[threadIdx.x], red[threadIdx.x+256]);
    __syncthreads();
    if (threadIdx.x < 128) g[b*128 + c] = fmaxf(red[threadIdx.x], red[threadIdx.x+128]);
}

__global__ void hg_kernel(const float* __restrict__ g, const float* __restrict__ w,
                          const float* __restrict__ b1, float* __restrict__ hg)
{
    int b = blockIdx.x, c = threadIdx.x;
    float acc = b1[c];
    for (int k = 0; k < 128; k++)
        acc = fmaf(g[b*128 + k], w[k*128 + c], acc);
    hg[b*128 + c] = acc;
}

// ---------------------------------------------------------------------------
// Pair kernel: 64x64 tiles, 256 threads, 4x4 micro, c in 2 chunks of 64.
// ---------------------------------------------------------------------------
__global__ void __launch_bounds__(256)
pair_kernel(const float* __restrict__ hi, const float* __restrict__ hj,
            const float* __restrict__ w2, const float* __restrict__ b2p,
            float* __restrict__ out)
{
    const int b  = blockIdx.z;
    const int i0 = blockIdx.y * 64;
    const int j0 = blockIdx.x * 64;
    if (j0 + 63 <= i0) return;

    __shared__ float shi[64][65];
    __shared__ float shj[64][65];
    __shared__ float sw2[128];

    const int tid = threadIdx.x;
    const int ti = tid >> 4;
    const int tj = tid & 15;

    if (tid < 128) sw2[tid] = w2[tid];

    float acc[4][4];
    #pragma unroll
    for (int q = 0; q < 4; q++)
        #pragma unroll
        for (int s = 0; s < 4; s++) acc[q][s] = 0.f;

    for (int c0 = 0; c0 < 128; c0 += 64) {
        __syncthreads();
        #pragma unroll
        for (int it = 0; it < 16; it++) {
            int idx = tid + it * 256;
            int r = idx >> 6, c = idx & 63;
            int gi = i0 + r, gj = j0 + r;
            shi[r][c] = (gi < NPTS) ? hi[(((size_t)b*NPTS) + gi)*128 + c0 + c] : 0.f;
            shj[r][c] = (gj < NPTS) ? hj[(((size_t)b*NPTS) + gj)*128 + c0 + c] : 0.f;
        }
        __syncthreads();
        #pragma unroll 8
        for (int c = 0; c < 64; c++) {
            float w = sw2[c0 + c];
            float ri[4], rj[4];
            #pragma unroll
            for (int q = 0; q < 4; q++) ri[q] = shi[ti*4 + q][c];
            #pragma unroll
            for (int s = 0; s < 4; s++) rj[s] = shj[tj + 16*s][c];
            #pragma unroll
            for (int q = 0; q < 4; q++)
                #pragma unroll
                for (int s = 0; s < 4; s++)
                    acc[q][s] = fmaf(fmaxf(ri[q] + rj[s], 0.f), w, acc[q][s]);
        }
    }

    const float bb = b2p[0];
    #pragma unroll
    for (int q = 0; q < 4; q++) {
        int i = i0 + ti*4 + q;
        if (i >= NPTS) continue;
        #pragma unroll
        for (int s = 0; s < 4; s++) {
            int j = j0 + tj + 16*s;
            if (j < NPTS && i < j) {
                float lg = acc[q][s] + bb;
                int p = i*NPTS - (i*(i+1))/2 + (j - i - 1);
                out[(size_t)b*NPAIR + p] = 1.f / (1.f + expf(-lg));
                out[(size_t)BATCH*NPAIR + (size_t)b*NPAIR + p] = lg;
            }
        }
    }
}

// ---------------------------------------------------------------------------
// Launch helpers
// ---------------------------------------------------------------------------
static inline void run_sgemm64(const float* A, const float* W, const float* bias,
                               float* C, int M, int N, int K, int relu)
{
    dim3 grid((N + 63)/64, (M + 63)/64);
    sgemm64_kernel<<<grid, 256>>>(A, W, bias, C, M, N, K, relu);
}

// db128: exact multiples M%128==0, N%128==0, K%16==0
static inline void run_db128(const float* AT, int lda, const float* W, const float* bias,
                             float* C, int M, int N, int K, int relu)
{
    dim3 grid(N/128, M/128);
    sgemm_db_kernel<128,128,16,8,8,false><<<grid, 256>>>(AT, lda, W, bias, C, M, N, K, relu);
}
// db64: N%64==0, K%32==0, M%4==0 (M-guarded)
static inline void run_db64(const float* AT, int lda, const float* W, const float* bias,
                            float* C, int M, int N, int K, int relu)
{
    dim3 grid(N/64, (M + 63)/64);
    sgemm_db_kernel<64,64,32,4,4,true><<<grid, 256>>>(AT, lda, W, bias, C, M, N, K, relu);
}

static inline void run_transpose(const float* in, float* outp, int M, int K)
{
    dim3 grid((K + 31)/32, (M + 31)/32);
    transpose_kernel<<<grid, 256>>>(in, outp, M, K);
}

template<int C>
static inline void run_knn(const float* x, float* sqb, float* d2, int* knn)
{
    sq_kernel<C><<<(BATCH*NPTS + 127)/128, 128>>>(x, sqb);
    dim3 dgrid((NPTS + 63)/64, (NPTS + 63)/64, BATCH);
    dist_kernel<C><<<dgrid, 256>>>(x, sqb, d2);
    dim3 tgrid(NPTS, BATCH);
    topk_kernel<<<tgrid, 128>>>(d2, knn);
}

extern "C" void kernel_launch(void* const* d_in, const int* in_sizes, int n_in,
                              void* d_out, int out_size)
{
    const float* pos   = (const float*)d_in[0];
    const float* c1_w1 = (const float*)d_in[1];
    const float* c1_b1 = (const float*)d_in[2];
    const float* c1_w2 = (const float*)d_in[3];
    const float* c1_b2 = (const float*)d_in[4];
    const float* c2_w1 = (const float*)d_in[5];
    const float* c2_b1 = (const float*)d_in[6];
    const float* c2_w2 = (const float*)d_in[7];
    const float* c2_b2 = (const float*)d_in[8];
    const float* c3_w1 = (const float*)d_in[9];
    const float* c3_b1 = (const float*)d_in[10];
    const float* c3_w2 = (const float*)d_in[11];
    const float* c3_b2 = (const float*)d_in[12];
    const float* sm_w1 = (const float*)d_in[13];
    const float* sm_b1 = (const float*)d_in[14];
    const float* sm_w2 = (const float*)d_in[15];
    const float* sm_b2 = (const float*)d_in[16];
    const float* ec_w1 = (const float*)d_in[17];
    const float* ec_b1 = (const float*)d_in[18];
    const float* ec_w2 = (const float*)d_in[19];
    const float* ec_b2 = (const float*)d_in[20];

    float* out = (float*)d_out;

    int*   knn;  cudaGetSymbolAddress((void**)&knn,  g_knn);
    float* sqb;  cudaGetSymbolAddress((void**)&sqb,  g_sq);
    float* d2;   cudaGetSymbolAddress((void**)&d2,   g_d2);
    float* Ab;   cudaGetSymbolAddress((void**)&Ab,   g_A);
    float* Bb;   cudaGetSymbolAddress((void**)&Bb,   g_B);
    float* H;    cudaGetSymbolAddress((void**)&H,    g_H);
    float* Msg;  cudaGetSymbolAddress((void**)&Msg,  g_Msg);
    float* T;    cudaGetSymbolAddress((void**)&T,    g_T);
    float* x1;   cudaGetSymbolAddress((void**)&x1,   g_x1);
    float* x2;   cudaGetSymbolAddress((void**)&x2,   g_x2);
    float* xcat; cudaGetSymbolAddress((void**)&xcat, g_xcat);
    float* sf;   cudaGetSymbolAddress((void**)&sf,   g_sf);
    float* hi;   cudaGetSymbolAddress((void**)&hi,   g_hi);
    float* hj;   cudaGetSymbolAddress((void**)&hj,   g_hj);
    float* gbuf; cudaGetSymbolAddress((void**)&gbuf, g_g);
    float* hg;   cudaGetSymbolAddress((void**)&hg,   g_hg);

    const int ROWS = BATCH*NPTS*KNN;   // 16000
    const int PTS  = BATCH*NPTS;       // 2000

    // ======== EdgeConv 1: pos (C=3) -> x1 (32) ========
    run_knn<3>(pos, sqb, d2, knn);
    edge1_kernel<<<(ROWS*16 + 255)/256, 256>>>(pos, knn, c1_w1, c1_b1, H);
    run_sgemm64(H, c1_w2, c1_b2, Msg, ROWS, 32, 16, 0);
    max_agg4_kernel<<<(PTS*8 + 255)/256, 256>>>(Msg, 8, x1, xcat, 0);

    // ======== EdgeConv 2: x1 (C=32) -> x2 (128) ========
    run_knn<32>(x1, sqb, d2, knn);
    run_sgemm64(x1, c2_w1,          nullptr, Ab, PTS, 64, 32, 0);
    run_sgemm64(x1, c2_w1 + 32*64,  nullptr, Bb, PTS, 64, 32, 0);
    edge_combine_kernel<<<(ROWS*16 + 255)/256, 256>>>(Ab, Bb, knn, c2_b1, H, 16);
    run_transpose(H, T, ROWS, 64);
    run_db128(T, ROWS, c2_w2, c2_b2, Msg, ROWS, 128, 64, 0);
    max_agg4_kernel<<<(PTS*32 + 255)/256, 256>>>(Msg, 32, x2, xcat, 32);

    // ======== EdgeConv 3: x2 (C=128) -> x3 (512) ========
    run_knn<128>(x2, sqb, d2, knn);
    run_transpose(x2, T, PTS, 128);
    run_db64(T, PTS, c3_w1,            nullptr, Ab, PTS, 256, 128, 0);
    run_db64(T, PTS, c3_w1 + 128*256,  nullptr, Bb, PTS, 256, 128, 0);
    edge_combine_kernel<<<(ROWS*64 + 255)/256, 256>>>(Ab, Bb, knn, c3_b1, H, 64);
    run_transpose(H, T, ROWS, 256);
    run_db128(T, ROWS, c3_w2, c3_b2, Msg, ROWS, 512, 256, 0);
    max_agg4_kernel<<<(PTS*128 + 255)/256, 256>>>(Msg, 128, nullptr, xcat, 160);

    // ======== shared MLP: xcat[2000,672] -> 256 (relu) -> sf[2000,128] ========
    run_transpose(xcat, T, PTS, 672);
    run_db64(T, PTS, sm_w1, sm_b1, H, PTS, 256, 672, 1);
    run_transpose(H, T, PTS, 256);
    run_db64(T, PTS, sm_w2, sm_b2, sf, PTS, 128, 256, 0);

    // ======== global pool + edge classifier pieces ========
    gpool_kernel<<<BATCH, 1024>>>(sf, gbuf);
    hg_kernel<<<BATCH, 128>>>(gbuf, ec_w1 + 256*128, ec_b1, hg);
    run_transpose(sf, T, PTS, 128);
    // hi' = sf @ W_hi + hg (per batch: AT columns are batch-contiguous)
    run_db64(T,        PTS, ec_w1, hg,       hi,            1000, 128, 128, 0);
    run_db64(T + 1000, PTS, ec_w1, hg + 128, hi + 1000*128, 1000, 128, 128, 0);
    run_db64(T,        PTS, ec_w1 + 128*128, nullptr, hj, PTS, 128, 128, 0);

    // ======== all-pairs classifier ========
    {
        dim3 grid((NPTS + 63)/64, (NPTS + 63)/64, BATCH);
        pair_kernel<<<grid, 256>>>(hi, hj, ec_w2, ec_b2, out);
    }
}

// round 7
// speedup vs baseline: 4.3008x; 1.1341x over previous
#include <cuda_runtime.h>
#include <cuda_bf16.h>
#include <math.h>
#include <float.h>
#include <stdint.h>

#define BATCH 2
#define NPTS  1000
#define KNN   8
#define NPAIR ((NPTS*(NPTS-1))/2)   // 499500

// ---------------------------------------------------------------------------
// Static scratch
// ---------------------------------------------------------------------------
__device__ int   g_knn [BATCH*NPTS*KNN];
__device__ float g_sq  [BATCH*NPTS];
__device__ float g_d2  [BATCH*NPTS*NPTS];      // 8 MB distance matrix
__device__ float g_A   [BATCH*NPTS*256];
__device__ float g_B   [BATCH*NPTS*256];
__device__ float g_H   [BATCH*NPTS*KNN*256];
__device__ float g_Msg [BATCH*NPTS*KNN*512];
__device__ float g_T   [16000*256];
__device__ float g_x1  [BATCH*NPTS*32];
__device__ float g_x2  [BATCH*NPTS*128];
__device__ float g_xcat[BATCH*NPTS*672];
__device__ float g_sf  [BATCH*NPTS*128];
__device__ float g_hi  [BATCH*NPTS*128];
__device__ float g_hj  [BATCH*NPTS*128];
__device__ float g_g   [BATCH*128];
__device__ float g_hg  [BATCH*128];
// bf16 split-concat buffers for the HMMA c3b GEMM (K' = 3*256 = 768)
__device__ __nv_bfloat16 g_Hcat[16000*768];    // [M][768] = [hi | hi | lo]
__device__ __nv_bfloat16 g_Wcat[512*768];      // [N][768] = [hi | lo | hi] (col-major B)

// ---------------------------------------------------------------------------
// cp.async helpers
// ---------------------------------------------------------------------------
__device__ __forceinline__ void cp_async16(void* smem_ptr, const void* gmem_ptr) {
    unsigned dst = (unsigned)__cvta_generic_to_shared(smem_ptr);
    asm volatile("cp.async.cg.shared.global [%0], [%1], 16;\n" :: "r"(dst), "l"(gmem_ptr));
}
__device__ __forceinline__ void cp_commit() { asm volatile("cp.async.commit_group;\n" ::: "memory"); }
__device__ __forceinline__ void cp_wait0()  { asm volatile("cp.async.wait_group 0;\n" ::: "memory"); }

// ---------------------------------------------------------------------------
// bf16 split prep: H[16000][256] -> Hcat[16000][768] = [hi | hi | lo]
// ---------------------------------------------------------------------------
__global__ void split_h3_kernel(const float* __restrict__ H,
                                __nv_bfloat16* __restrict__ Acat)
{
    int t = blockIdx.x * 256 + threadIdx.x;
    if (t >= 16000*256) return;
    int row = t >> 8, k = t & 255;
    float v = H[t];
    __nv_bfloat16 h = __float2bfloat16(v);
    __nv_bfloat16 l = __float2bfloat16(v - __bfloat162float(h));
    size_t base = (size_t)row * 768;
    Acat[base + k]       = h;
    Acat[base + 256 + k] = h;
    Acat[base + 512 + k] = l;
}

// W[256][512] -> Wcat[512][768] = [hi | lo | hi] (B col-major: [n][k])
__global__ void split_w3_kernel(const float* __restrict__ W,
                                __nv_bfloat16* __restrict__ Bcat)
{
    __shared__ float tile[32][33];
    int n0 = blockIdx.x * 32, k0 = blockIdx.y * 32;
    int tx = threadIdx.x & 31, ty = threadIdx.x >> 5;
    for (int r = ty; r < 32; r += 8) tile[r][tx] = W[(size_t)(k0+r)*512 + n0 + tx];
    __syncthreads();
    for (int r = ty; r < 32; r += 8) {
        float v = tile[tx][r];   // = W[k0+tx][n0+r]
        int n = n0 + r, k = k0 + tx;
        __nv_bfloat16 h = __float2bfloat16(v);
        __nv_bfloat16 l = __float2bfloat16(v - __bfloat162float(h));
        size_t base = (size_t)n * 768;
        Bcat[base + k]       = h;
        Bcat[base + 256 + k] = l;
        Bcat[base + 512 + k] = h;
    }
}

// ---------------------------------------------------------------------------
// HMMA bf16 GEMM for c3b: Msg[16000,512] = Acat @ Bcat^T + bias
// CTA tile 128x128, BK=32, double-buffered cp.async, 8 warps (2x4),
// warp tile 64x32 = 4x4 m16n8k16 atoms, fp32 accum.
// ---------------------------------------------------------------------------
__global__ void __launch_bounds__(256, 2)
c3b_mma_kernel(const __nv_bfloat16* __restrict__ Acat,   // [16000][768]
               const __nv_bfloat16* __restrict__ Bcat,   // [512][768]
               const float* __restrict__ bias,           // [512]
               float* __restrict__ C)                    // [16000][512]
{
    const int KTOT = 768, NOUT = 512;
    __shared__ __nv_bfloat16 sA[2][128][40];   // 40 bf16 = 80B row stride (bank-safe)
    __shared__ __nv_bfloat16 sB[2][128][40];

    const int tid  = threadIdx.x;
    const int wid  = tid >> 5;
    const int lane = tid & 31;
    const int m0 = blockIdx.x * 128;
    const int n0 = blockIdx.y * 128;
    const int wr = wid >> 2;     // 0..1 -> m offset wr*64
    const int wc = wid & 3;      // 0..3 -> n offset wc*32

    float acc[4][4][4];
    #pragma unroll
    for (int a = 0; a < 4; a++)
        #pragma unroll
        for (int b = 0; b < 4; b++)
            #pragma unroll
            for (int c = 0; c < 4; c++) acc[a][b][c] = 0.f;

    auto load_tile = [&](int buf, int k0) {
        #pragma unroll
        for (int t2 = 0; t2 < 2; t2++) {
            int c   = tid + t2 * 256;     // 0..511
            int row = c >> 2;             // 0..127
            int k8  = (c & 3) * 8;        // 0,8,16,24
            cp_async16(&sA[buf][row][k8], Acat + (size_t)(m0 + row)*KTOT + k0 + k8);
            cp_async16(&sB[buf][row][k8], Bcat + (size_t)(n0 + row)*KTOT + k0 + k8);
        }
    };

    load_tile(0, 0);
    cp_commit();
    int buf = 0;
    for (int k0 = 0; k0 < KTOT; k0 += 32) {
        cp_wait0();
        __syncthreads();
        if (k0 + 32 < KTOT) { load_tile(buf ^ 1, k0 + 32); cp_commit(); }

        #pragma unroll
        for (int ks = 0; ks < 2; ks++) {
            const int kb = ks * 16;
            uint32_t af[4][4], bf[4][2];
            #pragma unroll
            for (int ma = 0; ma < 4; ma++) {
                int m = wr*64 + ma*16 + (lane & 15);
                int k = kb + ((lane >> 4) << 3);
                uint32_t addr = (uint32_t)__cvta_generic_to_shared(&sA[buf][m][k]);
                asm volatile("ldmatrix.sync.aligned.m8n8.x4.shared.b16 {%0,%1,%2,%3}, [%4];"
                    : "=r"(af[ma][0]), "=r"(af[ma][1]), "=r"(af[ma][2]), "=r"(af[ma][3])
                    : "r"(addr));
            }
            #pragma unroll
            for (int na = 0; na < 4; na++) {
                int n = wc*32 + na*8 + (lane & 7);
                int k = kb + (lane & 8);
                uint32_t addr = (uint32_t)__cvta_generic_to_shared(&sB[buf][n][k]);
                asm volatile("ldmatrix.sync.aligned.m8n8.x2.shared.b16 {%0,%1}, [%2];"
                    : "=r"(bf[na][0]), "=r"(bf[na][1])
                    : "r"(addr));
            }
            #pragma unroll
            for (int ma = 0; ma < 4; ma++)
                #pragma unroll
                for (int na = 0; na < 4; na++)
                    asm volatile(
                        "mma.sync.aligned.m16n8k16.row.col.f32.bf16.bf16.f32 "
                        "{%0,%1,%2,%3}, {%4,%5,%6,%7}, {%8,%9}, {%0,%1,%2,%3};"
                        : "+f"(acc[ma][na][0]), "+f"(acc[ma][na][1]),
                          "+f"(acc[ma][na][2]), "+f"(acc[ma][na][3])
                        : "r"(af[ma][0]), "r"(af[ma][1]), "r"(af[ma][2]), "r"(af[ma][3]),
                          "r"(bf[na][0]), "r"(bf[na][1]));
        }
        buf ^= 1;
    }

    // epilogue: c0,c1 -> (m, n..n+1); c2,c3 -> (m+8, n..n+1)
    const int tm = lane >> 2;
    const int tn = (lane & 3) * 2;
    #pragma unroll
    for (int ma = 0; ma < 4; ma++) {
        #pragma unroll
        for (int na = 0; na < 4; na++) {
            int m = m0 + wr*64 + ma*16 + tm;
            int n = n0 + wc*32 + na*8 + tn;
            float b0 = bias[n], b1 = bias[n + 1];
            float2 v0 = make_float2(acc[ma][na][0] + b0, acc[ma][na][1] + b1);
            float2 v1 = make_float2(acc[ma][na][2] + b0, acc[ma][na][3] + b1);
            *reinterpret_cast<float2*>(&C[(size_t)m*NOUT + n])       = v0;
            *reinterpret_cast<float2*>(&C[(size_t)(m+8)*NOUT + n])   = v1;
        }
    }
}

// ---------------------------------------------------------------------------
// sq[b,n] = sum_c x^2
// ---------------------------------------------------------------------------
template<int C>
__global__ void sq_kernel(const float* __restrict__ x, float* __restrict__ sq)
{
    int t = blockIdx.x * blockDim.x + threadIdx.x;
    if (t >= BATCH*NPTS) return;
    const float* row = x + (size_t)t * C;
    float s = 0.f;
    #pragma unroll
    for (int c = 0; c < C; c++) s = fmaf(row[c], row[c], s);
    sq[t] = s;
}

// ---------------------------------------------------------------------------
// Pairwise distance
// ---------------------------------------------------------------------------
template<int C>
__global__ void __launch_bounds__(256)
dist_kernel(const float* __restrict__ x, const float* __restrict__ sq,
            float* __restrict__ d2)
{
    const int b  = blockIdx.z;
    const int n0 = blockIdx.y * 64;
    const int m0 = blockIdx.x * 64;
    const float* xb  = x  + (size_t)b * NPTS * C;
    const float* sqb = sq + b * NPTS;

    __shared__ float As[32][68];
    __shared__ float Bs[32][68];

    const int tid = threadIdx.x;
    const int ti = tid >> 4;
    const int tj = tid & 15;

    float acc[4][4];
    #pragma unroll
    for (int i = 0; i < 4; i++)
        #pragma unroll
        for (int j = 0; j < 4; j++) acc[i][j] = 0.f;

    for (int k0 = 0; k0 < C; k0 += 32) {
        #pragma unroll
        for (int v = tid; v < 512; v += 256) {
            int r  = v >> 3;
            int cq = (v & 7) * 4;
            {
                int row = n0 + r;
                float4 a4 = make_float4(0.f, 0.f, 0.f, 0.f);
                if (row < NPTS) {
                    if ((C & 31) == 0) {
                        a4 = *reinterpret_cast<const float4*>(&xb[(size_t)row*C + k0 + cq]);
                    } else {
                        float tmp[4];
                        #pragma unroll
                        for (int t2 = 0; t2 < 4; t2++) {
                            int k = k0 + cq + t2;
                            tmp[t2] = (k < C) ? xb[(size_t)row*C + k] : 0.f;
                        }
                        a4 = make_float4(tmp[0], tmp[1], tmp[2], tmp[3]);
                    }
                }
                As[cq+0][r] = a4.x; As[cq+1][r] = a4.y;
                As[cq+2][r] = a4.z; As[cq+3][r] = a4.w;
            }
            {
                int row = m0 + r;
                float4 b4 = make_float4(0.f, 0.f, 0.f, 0.f);
                if (row < NPTS) {
                    if ((C & 31) == 0) {
                        b4 = *reinterpret_cast<const float4*>(&xb[(size_t)row*C + k0 + cq]);
                    } else {
                        float tmp[4];
                        #pragma unroll
                        for (int t2 = 0; t2 < 4; t2++) {
                            int k = k0 + cq + t2;
                            tmp[t2] = (k < C) ? xb[(size_t)row*C + k] : 0.f;
                        }
                        b4 = make_float4(tmp[0], tmp[1], tmp[2], tmp[3]);
                    }
                }
                Bs[cq+0][r] = b4.x; Bs[cq+1][r] = b4.y;
                Bs[cq+2][r] = b4.z; Bs[cq+3][r] = b4.w;
            }
        }
        __syncthreads();
        #pragma unroll
        for (int kk = 0; kk < 32; kk++) {
            float ra[4], rb[4];
            *reinterpret_cast<float4*>(ra) = *reinterpret_cast<const float4*>(&As[kk][ti*4]);
            *reinterpret_cast<float4*>(rb) = *reinterpret_cast<const float4*>(&Bs[kk][tj*4]);
            #pragma unroll
            for (int i = 0; i < 4; i++)
                #pragma unroll
                for (int j = 0; j < 4; j++)
                    acc[i][j] = fmaf(ra[i], rb[j], acc[i][j]);
        }
        __syncthreads();
    }

    const int ni = n0 + ti*4;
    const int mj = m0 + tj*4;
    float sqi[4], sqj[4];
    #pragma unroll
    for (int i = 0; i < 4; i++) sqi[i] = (ni+i < NPTS) ? sqb[ni+i] : 0.f;
    #pragma unroll
    for (int j = 0; j < 4; j++) sqj[j] = (mj+j < NPTS) ? sqb[mj+j] : 0.f;
    #pragma unroll
    for (int i = 0; i < 4; i++) {
        if (ni+i >= NPTS) continue;
        #pragma unroll
        for (int j = 0; j < 4; j++) {
            if (mj+j >= NPTS) continue;
            d2[((size_t)b*NPTS + ni+i)*NPTS + mj+j] = sqi[i] + sqj[j] - 2.f*acc[i][j];
        }
    }
}

// ---------------------------------------------------------------------------
// Top-8 per row (ties -> lower idx)
// ---------------------------------------------------------------------------
__global__ void topk_kernel(const float* __restrict__ d2, int* __restrict__ knn)
{
    const int b = blockIdx.y;
    const int n = blockIdx.x;
    const int tid = threadIdx.x;   // 128
    const float* row = d2 + ((size_t)b*NPTS + n)*NPTS;

    __shared__ float sd[128*8];
    __shared__ int   si[128*8];

    float bd[8]; int bi[8];
    #pragma unroll
    for (int k = 0; k < 8; k++) { bd[k] = FLT_MAX; bi[k] = 0x7FFFFFFF; }

    for (int m = tid; m < NPTS; m += 128) {
        float d = row[m];
        if (d < bd[7] || (d == bd[7] && m < bi[7])) {
            int p = 7;
            #pragma unroll
            for (int it = 0; it < 7; it++) {
                if (p > 0 && (d < bd[p-1] || (d == bd[p-1] && m < bi[p-1]))) {
                    bd[p] = bd[p-1]; bi[p] = bi[p-1]; p--;
                }
            }
            bd[p] = d; bi[p] = m;
        }
    }
    #pragma unroll
    for (int k = 0; k < 8; k++) { sd[tid*8+k] = bd[k]; si[tid*8+k] = bi[k]; }

    for (int s = 64; s >= 1; s >>= 1) {
        __syncthreads();
        if (tid < s) {
            float* Ad = &sd[tid*8];        int* Ai = &si[tid*8];
            float* Bd = &sd[(tid+s)*8];    int* Bi = &si[(tid+s)*8];
            float od[8]; int oi[8];
            int a = 0, c2 = 0;
            #pragma unroll
            for (int o = 0; o < 8; o++) {
                bool ta = (Ad[a] < Bd[c2]) || (Ad[a] == Bd[c2] && Ai[a] < Bi[c2]);
                if (ta) { od[o] = Ad[a]; oi[o] = Ai[a]; a++; }
                else    { od[o] = Bd[c2]; oi[o] = Bi[c2]; c2++; }
            }
            #pragma unroll
            for (int o = 0; o < 8; o++) { Ad[o] = od[o]; Ai[o] = oi[o]; }
        }
    }
    __syncthreads();
    if (tid < 8) knn[((size_t)b*NPTS + n)*8 + tid] = si[tid];
}

// ---------------------------------------------------------------------------
// Transpose
// ---------------------------------------------------------------------------
__global__ void transpose_kernel(const float* __restrict__ in, float* __restrict__ outp,
                                 int M, int K)
{
    __shared__ float tile[32][33];
    const int k0 = blockIdx.x * 32;
    const int m0 = blockIdx.y * 32;
    const int tx = threadIdx.x & 31;
    const int ty = threadIdx.x >> 5;
    #pragma unroll
    for (int r = ty; r < 32; r += 8) {
        int m = m0 + r, k = k0 + tx;
        tile[r][tx] = (m < M && k < K) ? in[(size_t)m*K + k] : 0.f;
    }
    __syncthreads();
    #pragma unroll
    for (int r = ty; r < 32; r += 8) {
        int k = k0 + r, m = m0 + tx;
        if (k < K && m < M) outp[(size_t)k*M + m] = tile[tx][r];
    }
}

// ---------------------------------------------------------------------------
// Double-buffered cp.async SGEMM (AT layout)
// ---------------------------------------------------------------------------
template<int BM, int BN, int BK, int TM, int TN, bool GUARDM>
__global__ void __launch_bounds__(256, 2)
sgemm_db_kernel(const float* __restrict__ AT, int lda,
                const float* __restrict__ W,
                const float* __restrict__ bias, float* __restrict__ C,
                int M, int N, int K, int relu)
{
    __shared__ float As[2][BK][BM];
    __shared__ float Bs[2][BK][BN];

    const int tid = threadIdx.x;
    constexpr int NTX = BN / TN;
    const int tx = tid % NTX;
    const int ty = tid / NTX;
    const int row0 = blockIdx.y * BM;
    const int col0 = blockIdx.x * BN;

    float acc[TM][TN];
    #pragma unroll
    for (int i = 0; i < TM; i++)
        #pragma unroll
        for (int j = 0; j < TN; j++) acc[i][j] = 0.f;

    auto load_tile = [&](int buf, int k0) {
        constexpr int CHA = BM*BK/4;
        #pragma unroll
        for (int t = 0; t < CHA/256; t++) {
            int c  = tid + t*256;
            int kk = c / (BM/4);
            int m4 = (c % (BM/4)) * 4;
            int gm = row0 + m4;
            if (GUARDM) gm = min(gm, M - 4);
            cp_async16(&As[buf][kk][m4], &AT[(size_t)(k0+kk)*lda + gm]);
        }
        constexpr int CHB = BN*BK/4;
        #pragma unroll
        for (int t = 0; t < CHB/256; t++) {
            int c  = tid + t*256;
            int kk = c / (BN/4);
            int n4 = (c % (BN/4)) * 4;
            cp_async16(&Bs[buf][kk][n4], &W[(size_t)(k0+kk)*N + col0 + n4]);
        }
    };

    load_tile(0, 0);
    cp_commit();
    int buf = 0;
    for (int k0 = 0; k0 < K; k0 += BK) {
        cp_wait0();
        __syncthreads();
        if (k0 + BK < K) { load_tile(buf ^ 1, k0 + BK); cp_commit(); }
        #pragma unroll
        for (int kk = 0; kk < BK; kk++) {
            float ra[TM], rb[TN];
            #pragma unroll
            for (int i = 0; i < TM; i += 4)
                *reinterpret_cast<float4*>(&ra[i]) =
                    *reinterpret_cast<const float4*>(&As[buf][kk][ty*TM + i]);
            #pragma unroll
            for (int j = 0; j < TN; j += 4)
                *reinterpret_cast<float4*>(&rb[j]) =
                    *reinterpret_cast<const float4*>(&Bs[buf][kk][tx*TN + j]);
            #pragma unroll
            for (int i = 0; i < TM; i++)
                #pragma unroll
                for (int j = 0; j < TN; j++)
                    acc[i][j] = fmaf(ra[i], rb[j], acc[i][j]);
        }
        buf ^= 1;
    }

    float bvals[TN];
    #pragma unroll
    for (int j = 0; j < TN; j++)
        bvals[j] = bias ? bias[col0 + tx*TN + j] : 0.f;

    #pragma unroll
    for (int i = 0; i < TM; i++) {
        int gm = row0 + ty*TM + i;
        if (GUARDM && gm >= M) continue;
        #pragma unroll
        for (int j = 0; j < TN; j++) {
            float v = acc[i][j] + bvals[j];
            if (relu) v = fmaxf(v, 0.f);
            C[(size_t)gm * N + col0 + tx*TN + j] = v;
        }
    }
}

// ---------------------------------------------------------------------------
// Classic SGEMM 64x64 (A row-major)
// ---------------------------------------------------------------------------
__global__ void __launch_bounds__(256)
sgemm64_kernel(const float* __restrict__ A, const float* __restrict__ W,
               const float* __restrict__ bias, float* __restrict__ C,
               int M, int N, int K, int relu)
{
    __shared__ float As[16][64];
    __shared__ float Bs[16][64];

    const int tid = threadIdx.x;
    const int tx = tid & 15;
    const int ty = tid >> 4;
    const int row0 = blockIdx.y * 64;
    const int col0 = blockIdx.x * 64;

    float acc[4][4];
    #pragma unroll
    for (int i = 0; i < 4; i++)
        #pragma unroll
        for (int j = 0; j < 4; j++) acc[i][j] = 0.f;

    for (int k0 = 0; k0 < K; k0 += 16) {
        {
            int m  = tid >> 2;
            int kq = (tid & 3) * 4;
            int gm = row0 + m;
            float4 a4 = make_float4(0.f, 0.f, 0.f, 0.f);
            if (gm < M)
                a4 = *reinterpret_cast<const float4*>(&A[(size_t)gm * K + k0 + kq]);
            As[kq+0][m] = a4.x; As[kq+1][m] = a4.y;
            As[kq+2][m] = a4.z; As[kq+3][m] = a4.w;
        }
        {
            int kk = tid >> 4;
            int n4 = (tid & 15) * 4;
            int gn = col0 + n4;
            float4 b4 = make_float4(0.f, 0.f, 0.f, 0.f);
            if (gn < N)
                b4 = *reinterpret_cast<const float4*>(&W[(size_t)(k0 + kk) * N + gn]);
            *reinterpret_cast<float4*>(&Bs[kk][n4]) = b4;
        }
        __syncthreads();
        #pragma unroll
        for (int kk = 0; kk < 16; kk++) {
            float ra[4], rb[4];
            *reinterpret_cast<float4*>(ra) = *reinterpret_cast<const float4*>(&As[kk][ty*4]);
            *reinterpret_cast<float4*>(rb) = *reinterpret_cast<const float4*>(&Bs[kk][tx*4]);
            #pragma unroll
            for (int i = 0; i < 4; i++)
                #pragma unroll
                for (int j = 0; j < 4; j++)
                    acc[i][j] = fmaf(ra[i], rb[j], acc[i][j]);
        }
        __syncthreads();
    }
    #pragma unroll
    for (int i = 0; i < 4; i++) {
        int gm = row0 + ty*4 + i;
        if (gm >= M) continue;
        #pragma unroll
        for (int j = 0; j < 4; j++) {
            int gn = col0 + tx*4 + j;
            if (gn >= N) continue;
            float v = acc[i][j];
            if (bias) v += bias[gn];
            if (relu) v = fmaxf(v, 0.f);
            C[(size_t)gm * N + gn] = v;
        }
    }
}

// ---------------------------------------------------------------------------
// Stage-1 fused layer 1
// ---------------------------------------------------------------------------
__global__ void edge1_kernel(const float* __restrict__ pos, const int* __restrict__ knn,
                             const float* __restrict__ W1, const float* __restrict__ b1,
                             float* __restrict__ H)
{
    int t = blockIdx.x * blockDim.x + threadIdx.x;
    if (t >= BATCH*NPTS*KNN*16) return;
    int nh = t & 15;
    int e  = t >> 4;
    int n  = (e / KNN) % NPTS;
    int b  = e / (KNN*NPTS);
    int j  = knn[e];
    const float* xi = pos + (((size_t)b*NPTS) + n)*3;
    const float* xj = pos + (((size_t)b*NPTS) + j)*3;
    float acc = b1[nh];
    #pragma unroll
    for (int c = 0; c < 3; c++) {
        acc = fmaf(xi[c],          W1[c*16 + nh],     acc);
        acc = fmaf(xj[c] - xi[c],  W1[(3+c)*16 + nh], acc);
    }
    H[(size_t)e*16 + nh] = fmaxf(acc, 0.f);
}

// ---------------------------------------------------------------------------
// Edge combine
// ---------------------------------------------------------------------------
__global__ void edge_combine_kernel(const float* __restrict__ A,
                                    const float* __restrict__ Bv,
                                    const int* __restrict__ knn,
                                    const float* __restrict__ b1,
                                    float* __restrict__ H, int Nh4)
{
    int t = blockIdx.x * blockDim.x + threadIdx.x;
    int all = BATCH*NPTS*KNN*Nh4;
    if (t >= all) return;
    int c4 = t % Nh4;
    int e  = t / Nh4;
    int n  = (e / KNN) % NPTS;
    int b  = e / (KNN*NPTS);
    int j  = knn[e];
    size_t pi = (size_t)b*NPTS + n;
    size_t pj = (size_t)b*NPTS + j;
    float4 a  = reinterpret_cast<const float4*>(A)[pi*Nh4 + c4];
    float4 bi = reinterpret_cast<const float4*>(Bv)[pi*Nh4 + c4];
    float4 bj = reinterpret_cast<const float4*>(Bv)[pj*Nh4 + c4];
    float4 bb = reinterpret_cast<const float4*>(b1)[c4];
    float4 h;
    h.x = fmaxf(a.x + bj.x - bi.x + bb.x, 0.f);
    h.y = fmaxf(a.y + bj.y - bi.y + bb.y, 0.f);
    h.z = fmaxf(a.z + bj.z - bi.z + bb.z, 0.f);
    h.w = fmaxf(a.w + bj.w - bi.w + bb.w, 0.f);
    reinterpret_cast<float4*>(H)[(size_t)e*Nh4 + c4] = h;
}

// ---------------------------------------------------------------------------
// Max-aggregate over 8 neighbors (float4)
// ---------------------------------------------------------------------------
__global__ void max_agg4_kernel(const float* __restrict__ Msg, int Cout4,
                                float* __restrict__ xout,
                                float* __restrict__ xcat, int cat_off)
{
    int t = blockIdx.x * blockDim.x + threadIdx.x;
    int total = BATCH*NPTS*Cout4;
    if (t >= total) return;
    int c4 = t % Cout4;
    int p  = t / Cout4;
    float4 v = make_float4(-FLT_MAX, -FLT_MAX, -FLT_MAX, -FLT_MAX);
    #pragma unroll
    for (int k = 0; k < KNN; k++) {
        float4 m = reinterpret_cast<const float4*>(Msg)[((size_t)p*KNN + k)*Cout4 + c4];
        v.x = fmaxf(v.x, m.x); v.y = fmaxf(v.y, m.y);
        v.z = fmaxf(v.z, m.z); v.w = fmaxf(v.w, m.w);
    }
    if (xout) reinterpret_cast<float4*>(xout)[(size_t)p*Cout4 + c4] = v;
    reinterpret_cast<float4*>(&xcat[(size_t)p*672 + cat_off])[c4] = v;
}

// ---------------------------------------------------------------------------
// Global max pool / hg
// ---------------------------------------------------------------------------
__global__ void gpool_kernel(const float* __restrict__ sf, float* __restrict__ g)
{
    __shared__ float red[1024];
    int b = blockIdx.x;
    int c = threadIdx.x & 127;
    int slice = threadIdx.x >> 7;
    float v = -FLT_MAX;
    for (int n = slice; n < NPTS; n += 8)
        v = fmaxf(v, sf[(((size_t)b*NPTS) + n)*128 + c]);
    red[threadIdx.x] = v;
    __syncthreads();
    if (threadIdx.x < 512) red[threadIdx.x] = fmaxf(red[threadIdx.x], red[threadIdx.x+512]);
    __syncthreads();
    if (threadIdx.x < 256) red[threadIdx.x] = fmaxf(red[threadIdx.x], red[threadIdx.x+256]);
    __syncthreads();
    if (threadIdx.x < 128) g[b*128 + c] = fmaxf(red[threadIdx.x], red[threadIdx.x+128]);
}

__global__ void hg_kernel(const float* __restrict__ g, const float* __restrict__ w,
                          const float* __restrict__ b1, float* __restrict__ hg)
{
    int b = blockIdx.x, c = threadIdx.x;
    float acc = b1[c];
    for (int k = 0; k < 128; k++)
        acc = fmaf(g[b*128 + k], w[k*128 + c], acc);
    hg[b*128 + c] = acc;
}

// ---------------------------------------------------------------------------
// Pair kernel
// ---------------------------------------------------------------------------
__global__ void __launch_bounds__(256)
pair_kernel(const float* __restrict__ hi, const float* __restrict__ hj,
            const float* __restrict__ w2, const float* __restrict__ b2p,
            float* __restrict__ out)
{
    const int b  = blockIdx.z;
    const int i0 = blockIdx.y * 64;
    const int j0 = blockIdx.x * 64;
    if (j0 + 63 <= i0) return;

    __shared__ float shi[64][65];
    __shared__ float shj[64][65];
    __shared__ float sw2[128];

    const int tid = threadIdx.x;
    const int ti = tid >> 4;
    const int tj = tid & 15;

    if (tid < 128) sw2[tid] = w2[tid];

    float acc[4][4];
    #pragma unroll
    for (int q = 0; q < 4; q++)
        #pragma unroll
        for (int s = 0; s < 4; s++) acc[q][s] = 0.f;

    for (int c0 = 0; c0 < 128; c0 += 64) {
        __syncthreads();
        #pragma unroll
        for (int it = 0; it < 16; it++) {
            int idx = tid + it * 256;
            int r = idx >> 6, c = idx & 63;
            int gi = i0 + r, gj = j0 + r;
            shi[r][c] = (gi < NPTS) ? hi[(((size_t)b*NPTS) + gi)*128 + c0 + c] : 0.f;
            shj[r][c] = (gj < NPTS) ? hj[(((size_t)b*NPTS) + gj)*128 + c0 + c] : 0.f;
        }
        __syncthreads();
        #pragma unroll 8
        for (int c = 0; c < 64; c++) {
            float w = sw2[c0 + c];
            float ri[4], rj[4];
            #pragma unroll
            for (int q = 0; q < 4; q++) ri[q] = shi[ti*4 + q][c];
            #pragma unroll
            for (int s = 0; s < 4; s++) rj[s] = shj[tj + 16*s][c];
            #pragma unroll
            for (int q = 0; q < 4; q++)
                #pragma unroll
                for (int s = 0; s < 4; s++)
                    acc[q][s] = fmaf(fmaxf(ri[q] + rj[s], 0.f), w, acc[q][s]);
        }
    }

    const float bb = b2p[0];
    #pragma unroll
    for (int q = 0; q < 4; q++) {
        int i = i0 + ti*4 + q;
        if (i >= NPTS) continue;
        #pragma unroll
        for (int s = 0; s < 4; s++) {
            int j = j0 + tj + 16*s;
            if (j < NPTS && i < j) {
                float lg = acc[q][s] + bb;
                int p = i*NPTS - (i*(i+1))/2 + (j - i - 1);
                out[(size_t)b*NPAIR + p] = 1.f / (1.f + expf(-lg));
                out[(size_t)BATCH*NPAIR + (size_t)b*NPAIR + p] = lg;
            }
        }
    }
}

// ---------------------------------------------------------------------------
// Launch helpers
// ---------------------------------------------------------------------------
static inline void run_sgemm64(const float* A, const float* W, const float* bias,
                               float* C, int M, int N, int K, int relu)
{
    dim3 grid((N + 63)/64, (M + 63)/64);
    sgemm64_kernel<<<grid, 256>>>(A, W, bias, C, M, N, K, relu);
}
static inline void run_db128(const float* AT, int lda, const float* W, const float* bias,
                             float* C, int M, int N, int K, int relu)
{
    dim3 grid(N/128, M/128);
    sgemm_db_kernel<128,128,16,8,8,false><<<grid, 256>>>(AT, lda, W, bias, C, M, N, K, relu);
}
static inline void run_db64(const float* AT, int lda, const float* W, const float* bias,
                            float* C, int M, int N, int K, int relu)
{
    dim3 grid(N/64, (M + 63)/64);
    sgemm_db_kernel<64,64,32,4,4,true><<<grid, 256>>>(AT, lda, W, bias, C, M, N, K, relu);
}
static inline void run_transpose(const float* in, float* outp, int M, int K)
{
    dim3 grid((K + 31)/32, (M + 31)/32);
    transpose_kernel<<<grid, 256>>>(in, outp, M, K);
}
template<int C>
static inline void run_knn(const float* x, float* sqb, float* d2, int* knn)
{
    sq_kernel<C><<<(BATCH*NPTS + 127)/128, 128>>>(x, sqb);
    dim3 dgrid((NPTS + 63)/64, (NPTS + 63)/64, BATCH);
    dist_kernel<C><<<dgrid, 256>>>(x, sqb, d2);
    dim3 tgrid(NPTS, BATCH);
    topk_kernel<<<tgrid, 128>>>(d2, knn);
}

extern "C" void kernel_launch(void* const* d_in, const int* in_sizes, int n_in,
                              void* d_out, int out_size)
{
    const float* pos   = (const float*)d_in[0];
    const float* c1_w1 = (const float*)d_in[1];
    const float* c1_b1 = (const float*)d_in[2];
    const float* c1_w2 = (const float*)d_in[3];
    const float* c1_b2 = (const float*)d_in[4];
    const float* c2_w1 = (const float*)d_in[5];
    const float* c2_b1 = (const float*)d_in[6];
    const float* c2_w2 = (const float*)d_in[7];
    const float* c2_b2 = (const float*)d_in[8];
    const float* c3_w1 = (const float*)d_in[9];
    const float* c3_b1 = (const float*)d_in[10];
    const float* c3_w2 = (const float*)d_in[11];
    const float* c3_b2 = (const float*)d_in[12];
    const float* sm_w1 = (const float*)d_in[13];
    const float* sm_b1 = (const float*)d_in[14];
    const float* sm_w2 = (const float*)d_in[15];
    const float* sm_b2 = (const float*)d_in[16];
    const float* ec_w1 = (const float*)d_in[17];
    const float* ec_b1 = (const float*)d_in[18];
    const float* ec_w2 = (const float*)d_in[19];
    const float* ec_b2 = (const float*)d_in[20];

    float* out = (float*)d_out;

    int*   knn;  cudaGetSymbolAddress((void**)&knn,  g_knn);
    float* sqb;  cudaGetSymbolAddress((void**)&sqb,  g_sq);
    float* d2;   cudaGetSymbolAddress((void**)&d2,   g_d2);
    float* Ab;   cudaGetSymbolAddress((void**)&Ab,   g_A);
    float* Bb;   cudaGetSymbolAddress((void**)&Bb,   g_B);
    float* H;    cudaGetSymbolAddress((void**)&H,    g_H);
    float* Msg;  cudaGetSymbolAddress((void**)&Msg,  g_Msg);
    float* T;    cudaGetSymbolAddress((void**)&T,    g_T);
    float* x1;   cudaGetSymbolAddress((void**)&x1,   g_x1);
    float* x2;   cudaGetSymbolAddress((void**)&x2,   g_x2);
    float* xcat; cudaGetSymbolAddress((void**)&xcat, g_xcat);
    float* sf;   cudaGetSymbolAddress((void**)&sf,   g_sf);
    float* hi;   cudaGetSymbolAddress((void**)&hi,   g_hi);
    float* hj;   cudaGetSymbolAddress((void**)&hj,   g_hj);
    float* gbuf; cudaGetSymbolAddress((void**)&gbuf, g_g);
    float* hg;   cudaGetSymbolAddress((void**)&hg,   g_hg);
    __nv_bfloat16 *Hcat, *Wcat;
    cudaGetSymbolAddress((void**)&Hcat, g_Hcat);
    cudaGetSymbolAddress((void**)&Wcat, g_Wcat);

    const int ROWS = BATCH*NPTS*KNN;   // 16000
    const int PTS  = BATCH*NPTS;       // 2000

    // ======== EdgeConv 1: pos (C=3) -> x1 (32) ========
    run_knn<3>(pos, sqb, d2, knn);
    edge1_kernel<<<(ROWS*16 + 255)/256, 256>>>(pos, knn, c1_w1, c1_b1, H);
    run_sgemm64(H, c1_w2, c1_b2, Msg, ROWS, 32, 16, 0);
    max_agg4_kernel<<<(PTS*8 + 255)/256, 256>>>(Msg, 8, x1, xcat, 0);

    // ======== EdgeConv 2: x1 (C=32) -> x2 (128) ========
    run_knn<32>(x1, sqb, d2, knn);
    run_sgemm64(x1, c2_w1,          nullptr, Ab, PTS, 64, 32, 0);
    run_sgemm64(x1, c2_w1 + 32*64,  nullptr, Bb, PTS, 64, 32, 0);
    edge_combine_kernel<<<(ROWS*16 + 255)/256, 256>>>(Ab, Bb, knn, c2_b1, H, 16);
    run_transpose(H, T, ROWS, 64);
    run_db128(T, ROWS, c2_w2, c2_b2, Msg, ROWS, 128, 64, 0);
    max_agg4_kernel<<<(PTS*32 + 255)/256, 256>>>(Msg, 32, x2, xcat, 32);

    // ======== EdgeConv 3: x2 (C=128) -> x3 (512) ========
    run_knn<128>(x2, sqb, d2, knn);
    run_transpose(x2, T, PTS, 128);
    run_db64(T, PTS, c3_w1,            nullptr, Ab, PTS, 256, 128, 0);
    run_db64(T, PTS, c3_w1 + 128*256,  nullptr, Bb, PTS, 256, 128, 0);
    edge_combine_kernel<<<(ROWS*64 + 255)/256, 256>>>(Ab, Bb, knn, c3_b1, H, 64);
    // --- c3b on tensor cores (HMMA bf16, split-concat K'=768) ---
    split_h3_kernel<<<(16000*256 + 255)/256, 256>>>(H, Hcat);
    split_w3_kernel<<<dim3(512/32, 256/32), 256>>>(c3_w2, Wcat);
    c3b_mma_kernel<<<dim3(125, 4), 256>>>(Hcat, Wcat, c3_b2, Msg);
    max_agg4_kernel<<<(PTS*128 + 255)/256, 256>>>(Msg, 128, nullptr, xcat, 160);

    // ======== shared MLP: xcat[2000,672] -> 256 (relu) -> sf[2000,128] ========
    run_transpose(xcat, T, PTS, 672);
    run_db64(T, PTS, sm_w1, sm_b1, H, PTS, 256, 672, 1);
    run_transpose(H, T, PTS, 256);
    run_db64(T, PTS, sm_w2, sm_b2, sf, PTS, 128, 256, 0);

    // ======== global pool + edge classifier pieces ========
    gpool_kernel<<<BATCH, 1024>>>(sf, gbuf);
    hg_kernel<<<BATCH, 128>>>(gbuf, ec_w1 + 256*128, ec_b1, hg);
    run_transpose(sf, T, PTS, 128);
    run_db64(T,        PTS, ec_w1, hg,       hi,            1000, 128, 128, 0);
    run_db64(T + 1000, PTS, ec_w1, hg + 128, hi + 1000*128, 1000, 128, 128, 0);
    run_db64(T,        PTS, ec_w1 + 128*128, nullptr, hj, PTS, 128, 128, 0);

    // ======== all-pairs classifier ========
    {
        dim3 grid((NPTS + 63)/64, (NPTS + 63)/64, BATCH);
        pair_kernel<<<grid, 256>>>(hi, hj, ec_w2, ec_b2, out);
    }
}